// round 1
// baseline (speedup 1.0000x reference)
#include <cuda_runtime.h>
#include <math.h>

#define BATCH 512
#define MDIM  128
#define N3    381

// ---------------- scratch (device globals: allocation-free) ----------------
__device__ float g_x1[(size_t)BATCH * 512 * 128];
__device__ float g_x2[(size_t)BATCH * 512 * 128];
__device__ float g_emb[(size_t)BATCH * 256 * 128];
__device__ float g_stats1[2 * BATCH];
__device__ float g_stats2[2 * BATCH];

// ---------------- tree conv as gathered GEMM ----------------
// out[b,h,j+1] = sum_{c,k} w[h,c,k] * T(in[b,c, idx[b,3j+k]]),  out[b,h,0]=0
// T = identity (MODE 0) or relu((v-mean_b)*inv_b) (MODE 1, fused layernorm of prev layer)
template<int CIN, int MODE>
__global__ __launch_bounds__(256)
void conv_kernel(const float* __restrict__ in, const int* __restrict__ idxg,
                 const float* __restrict__ w, const float* __restrict__ bias,
                 const float* __restrict__ stats, float* __restrict__ out, int Hout)
{
    const int b   = blockIdx.y;
    const int h0  = blockIdx.x * 64;
    const int tid = threadIdx.x;
    const int nt  = tid & 31;   // 32 groups along n, 4 n each
    const int hg  = tid >> 5;   // 8 groups along h, 8 h each
    const int K   = CIN * 3;

    __shared__ int   idx_s[384];
    __shared__ float data_s[8][128];
    __shared__ float g_s[24][128];
    __shared__ float w_s[24][64];

    float mean = 0.f, inv = 1.f;
    if (MODE == 1) { mean = stats[2*b]; inv = stats[2*b+1]; }

    for (int i = tid; i < 384; i += 256) idx_s[i] = (i < N3) ? idxg[b * N3 + i] : 0;

    float acc[8][4];
    #pragma unroll
    for (int i = 0; i < 8; i++)
        #pragma unroll
        for (int j = 0; j < 4; j++) acc[i][j] = 0.f;

    const float* inb = in + (size_t)b * CIN * 128;

    for (int c0 = 0; c0 < CIN; c0 += 8) {
        __syncthreads();   // previous GEMM step done before restaging
        // stage 8 input rows (apply fused norm+relu transform once per element)
        {
            int cl = tid >> 5, v = tid & 31;
            float4 d = *(const float4*)(inb + (size_t)(c0 + cl) * 128 + v * 4);
            if (MODE == 1) {
                d.x = fmaxf((d.x - mean) * inv, 0.f);
                d.y = fmaxf((d.y - mean) * inv, 0.f);
                d.z = fmaxf((d.z - mean) * inv, 0.f);
                d.w = fmaxf((d.w - mean) * inv, 0.f);
            }
            *(float4*)&data_s[cl][v * 4] = d;
        }
        // stage W tile transposed: w_s[kk][i]
        #pragma unroll
        for (int e = tid; e < 24 * 64; e += 256) {
            int i = e / 24, kk = e % 24;
            w_s[kk][i] = w[(size_t)(h0 + i) * K + c0 * 3 + kk];
        }
        __syncthreads();
        // gather G tile: g_s[kk][j] = data_s[kk/3][idx[3j + kk%3]]
        #pragma unroll
        for (int e = tid; e < 24 * 128; e += 256) {
            int kk = e >> 7, j = e & 127;
            int c_l = kk / 3, k = kk - c_l * 3;
            g_s[kk][j] = (j < 127) ? data_s[c_l][idx_s[3 * j + k]] : 0.f;
        }
        __syncthreads();
        // register-blocked GEMM step
        #pragma unroll
        for (int kk = 0; kk < 24; kk++) {
            float4 gv = *(const float4*)&g_s[kk][nt * 4];
            float4 w0 = *(const float4*)&w_s[kk][hg * 8];
            float4 w1 = *(const float4*)&w_s[kk][hg * 8 + 4];
            float wv[8] = {w0.x, w0.y, w0.z, w0.w, w1.x, w1.y, w1.z, w1.w};
            #pragma unroll
            for (int i = 0; i < 8; i++) {
                acc[i][0] += wv[i] * gv.x;
                acc[i][1] += wv[i] * gv.y;
                acc[i][2] += wv[i] * gv.z;
                acc[i][3] += wv[i] * gv.w;
            }
        }
    }

    float* outb = out + (size_t)b * Hout * 128;
    #pragma unroll
    for (int i = 0; i < 8; i++) {
        int h = h0 + hg * 8 + i;
        float bb = bias[h];
        #pragma unroll
        for (int u = 0; u < 4; u++) {
            int j = nt * 4 + u;
            if (j < 127) outb[(size_t)h * 128 + j + 1] = acc[i][u] + bb;
        }
    }
    if (tid < 64) outb[(size_t)(h0 + tid) * 128] = 0.f;   // zero column
}

// ---------------- per-batch layernorm stats (mean, 1/(std+1e-5), ddof=1) ----------------
__global__ __launch_bounds__(256)
void stats_kernel(const float* __restrict__ x, float* __restrict__ stats, int HN)
{
    int b = blockIdx.x, tid = threadIdx.x;
    const float* xb = x + (size_t)b * HN;
    double s = 0.0, s2 = 0.0;
    for (int i = tid * 4; i < HN; i += 256 * 4) {
        float4 v = *(const float4*)(xb + i);
        s  += (double)v.x + (double)v.y + (double)v.z + (double)v.w;
        s2 += (double)v.x * v.x + (double)v.y * v.y + (double)v.z * v.z + (double)v.w * v.w;
    }
    __shared__ double ss[256], ss2[256];
    ss[tid] = s; ss2[tid] = s2;
    __syncthreads();
    for (int o = 128; o > 0; o >>= 1) {
        if (tid < o) { ss[tid] += ss[tid + o]; ss2[tid] += ss2[tid + o]; }
        __syncthreads();
    }
    if (tid == 0) {
        double N = (double)HN;
        double mean = ss[0] / N;
        double var = (ss2[0] - ss[0] * ss[0] / N) / (N - 1.0);
        if (var < 0.0) var = 0.0;
        stats[2 * b]     = (float)mean;
        stats[2 * b + 1] = (float)(1.0 / (sqrt(var) + 1e-5));
    }
}

// ---------------- gate + softmax + attention pool + combined ----------------
// smem: et[128][257] | gw1c[32*128] | red[512] | logits[128] | rtmp[32]
#define GATE_SMEM_FLOATS (128 * 257 + 32 * 128 + 512 + 128 + 32)
__global__ __launch_bounds__(512, 1)
void gate_kernel(const float* __restrict__ emb, const float* __restrict__ gw1,
                 const float* __restrict__ gb1, const float* __restrict__ gw2,
                 const float* __restrict__ gb2, float* __restrict__ comb)
{
    extern __shared__ float sm[];
    float* et     = sm;                    // [128][257] : et[n][f]
    float* gw1c   = et + 128 * 257;        // [32][128]  : gw1c[fl][h]
    float* red    = gw1c + 32 * 128;       // [4][128]
    float* logits = red + 512;             // [128]
    float* rtmp   = logits + 128;          // [32]

    int b = blockIdx.x, tid = threadIdx.x;
    int n = tid & 127, hgrp = tid >> 7;    // hgrp 0..3
    const float* eb = emb + (size_t)b * 256 * 128;

    for (int e = tid; e < 256 * 128; e += 512) {
        int f = e >> 7, nn = e & 127;
        et[nn * 257 + f] = eb[e];
    }
    __syncthreads();

    float acc[32];
    #pragma unroll
    for (int s = 0; s < 32; s++) acc[s] = gb1[hgrp * 32 + s];

    for (int fc = 0; fc < 256; fc += 32) {
        for (int e = tid; e < 128 * 32; e += 512) {
            int h = e >> 5, fl = e & 31;
            gw1c[fl * 128 + h] = gw1[h * 256 + fc + fl];
        }
        __syncthreads();
        #pragma unroll 8
        for (int fl = 0; fl < 32; fl++) {
            float v = et[n * 257 + fc + fl];
            const float4* wp = (const float4*)&gw1c[fl * 128 + hgrp * 32];
            #pragma unroll
            for (int q = 0; q < 8; q++) {
                float4 w4 = wp[q];
                acc[q * 4 + 0] += v * w4.x;
                acc[q * 4 + 1] += v * w4.y;
                acc[q * 4 + 2] += v * w4.z;
                acc[q * 4 + 3] += v * w4.w;
            }
        }
        __syncthreads();
    }
    // gate2 partial: sum over this thread's 32 h of relu(gate1)*gw2[h]
    float p = 0.f;
    #pragma unroll
    for (int s = 0; s < 32; s++) p += fmaxf(acc[s], 0.f) * gw2[hgrp * 32 + s];
    red[hgrp * 128 + n] = p;
    __syncthreads();
    if (tid < 128)
        logits[tid] = red[tid] + red[128 + tid] + red[256 + tid] + red[384 + tid] + gb2[0];
    __syncthreads();
    // softmax over n (128)
    if (tid < 128) {
        float v = logits[tid];
        for (int o = 16; o > 0; o >>= 1) v = fmaxf(v, __shfl_xor_sync(0xffffffffu, v, o));
        if ((tid & 31) == 0) rtmp[tid >> 5] = v;
    }
    __syncthreads();
    float gmax = fmaxf(fmaxf(rtmp[0], rtmp[1]), fmaxf(rtmp[2], rtmp[3]));
    if (tid < 128) logits[tid] = expf(logits[tid] - gmax);
    __syncthreads();
    if (tid < 128) {
        float v = logits[tid];
        for (int o = 16; o > 0; o >>= 1) v += __shfl_xor_sync(0xffffffffu, v, o);
        if ((tid & 31) == 0) rtmp[4 + (tid >> 5)] = v;
    }
    __syncthreads();
    float rinv = 1.f / (rtmp[4] + rtmp[5] + rtmp[6] + rtmp[7]);
    if (tid < 128) logits[tid] *= rinv;
    __syncthreads();
    // pool + combined write
    if (tid < 256) {
        float pv = 0.f;
        #pragma unroll 8
        for (int nn = 0; nn < 128; nn++) pv += logits[nn] * et[nn * 257 + tid];
        comb[(size_t)b * 512 + tid]       = et[1 * 257 + tid];   // root = et[:,1,:]
        comb[(size_t)b * 512 + 256 + tid] = pv;                  // pool
    }
}

// ---------------- tiny MLP head: 512 -> 128 -> 64 -> 1 ----------------
__global__ __launch_bounds__(128)
void head_kernel(const float* __restrict__ comb,
                 const float* __restrict__ rw1, const float* __restrict__ rb1,
                 const float* __restrict__ rw2, const float* __restrict__ rb2,
                 const float* __restrict__ rw3, const float* __restrict__ rb3,
                 float* __restrict__ outv)
{
    __shared__ float cs[512];
    __shared__ float wc[128][33];
    __shared__ float h1[128];
    __shared__ float h2[64];
    int b = blockIdx.x, tid = threadIdx.x;

    for (int i = tid; i < 512; i += 128) cs[i] = comb[(size_t)b * 512 + i];

    float a = rb1[tid];
    for (int i0 = 0; i0 < 512; i0 += 32) {
        for (int e = tid; e < 128 * 32; e += 128) {
            int h = e >> 5, il = e & 31;
            wc[h][il] = rw1[h * 512 + i0 + il];
        }
        __syncthreads();
        #pragma unroll
        for (int il = 0; il < 32; il++) a += cs[i0 + il] * wc[tid][il];
        __syncthreads();
    }
    h1[tid] = fmaxf(a, 0.f);
    __syncthreads();

    float a2 = (tid < 64) ? rb2[tid] : 0.f;
    for (int i0 = 0; i0 < 128; i0 += 32) {
        for (int e = tid; e < 64 * 32; e += 128) {
            int h = e >> 5, il = e & 31;
            wc[h][il] = rw2[h * 128 + i0 + il];
        }
        __syncthreads();
        if (tid < 64) {
            #pragma unroll
            for (int il = 0; il < 32; il++) a2 += h1[i0 + il] * wc[tid][il];
        }
        __syncthreads();
    }
    if (tid < 64) h2[tid] = fmaxf(a2, 0.f);
    __syncthreads();

    if (tid < 64) {
        float p = h2[tid] * rw3[tid];
        for (int o = 16; o > 0; o >>= 1) p += __shfl_xor_sync(0xffffffffu, p, o);
        if ((tid & 31) == 0) h1[64 + (tid >> 5)] = p;   // reuse tail of h1
    }
    __syncthreads();
    if (tid == 0) outv[b] = h1[64] + h1[65] + rb3[0];
}

// ---------------- launch ----------------
extern "C" void kernel_launch(void* const* d_in, const int* in_sizes, int n_in,
                              void* d_out, int out_size)
{
    const float* trees = (const float*)d_in[0];
    const int*   idx   = (const int*)  d_in[1];
    const float* w1    = (const float*)d_in[2];
    const float* b1    = (const float*)d_in[3];
    const float* w2    = (const float*)d_in[4];
    const float* b2    = (const float*)d_in[5];
    const float* w3    = (const float*)d_in[6];
    const float* b3    = (const float*)d_in[7];
    const float* gw1   = (const float*)d_in[8];
    const float* gb1   = (const float*)d_in[9];
    const float* gw2   = (const float*)d_in[10];
    const float* gb2   = (const float*)d_in[11];
    const float* rw1   = (const float*)d_in[12];
    const float* rb1   = (const float*)d_in[13];
    const float* rw2   = (const float*)d_in[14];
    const float* rb2   = (const float*)d_in[15];
    const float* rw3   = (const float*)d_in[16];
    const float* rb3   = (const float*)d_in[17];

    float* out  = (float*)d_out;        // [512] final scores
    float* comb = out + 512;            // [512][512] combined

    float *x1, *x2, *embp, *st1, *st2;
    cudaGetSymbolAddress((void**)&x1,   g_x1);
    cudaGetSymbolAddress((void**)&x2,   g_x2);
    cudaGetSymbolAddress((void**)&embp, g_emb);
    cudaGetSymbolAddress((void**)&st1,  g_stats1);
    cudaGetSymbolAddress((void**)&st2,  g_stats2);

    size_t gate_smem = (size_t)GATE_SMEM_FLOATS * sizeof(float);
    cudaFuncSetAttribute(gate_kernel, cudaFuncAttributeMaxDynamicSharedMemorySize,
                         (int)gate_smem);

    // layer 1: raw trees -> x1 (raw conv out + bias, col0 = 0)
    conv_kernel<200, 0><<<dim3(8, BATCH), 256>>>(trees, idx, w1, b1, nullptr, x1, 512);
    stats_kernel<<<BATCH, 256>>>(x1, st1, 512 * 128);
    // layer 2: norm+relu(x1) -> x2
    conv_kernel<512, 1><<<dim3(8, BATCH), 256>>>(x1, idx, w2, b2, st1, x2, 512);
    stats_kernel<<<BATCH, 256>>>(x2, st2, 512 * 128);
    // layer 3: norm+relu(x2) -> emb (no norm after)
    conv_kernel<512, 1><<<dim3(4, BATCH), 256>>>(x2, idx, w3, b3, st2, embp, 256);
    // attention pool + combined
    gate_kernel<<<BATCH, 512, gate_smem>>>(embp, gw1, gb1, gw2, gb2, comb);
    // MLP head
    head_kernel<<<BATCH, 128>>>(comb, rw1, rb1, rw2, rb2, rw3, rb3, out);
}

// round 2
// speedup vs baseline: 1.0473x; 1.0473x over previous
#include <cuda_runtime.h>
#include <math.h>

#define BATCH 512
#define MDIM  128
#define N3    381

typedef unsigned long long u64;

// ---------------- scratch (device globals: allocation-free) ----------------
__device__ float g_x1[(size_t)BATCH * 512 * 128];
__device__ float g_x2[(size_t)BATCH * 512 * 128];
__device__ float g_emb[(size_t)BATCH * 256 * 128];
__device__ float g_stats[4 * BATCH];   // [0:2B) layer1 {sum,sumsq}, [2B:4B) layer2

// ---------------- packed fp32x2 helpers ----------------
__device__ __forceinline__ u64 fma2(u64 a, u64 b, u64 c) {
    u64 d;
    asm("fma.rn.f32x2 %0, %1, %2, %3;" : "=l"(d) : "l"(a), "l"(b), "l"(c));
    return d;
}
__device__ __forceinline__ u64 rep2(float x) {
    u64 d;
    asm("mov.b64 %0, {%1, %1};" : "=l"(d) : "f"(x));
    return d;
}
__device__ __forceinline__ float2 unpk(u64 a) {
    float2 r;
    asm("mov.b64 {%0, %1}, %2;" : "=f"(r.x), "=f"(r.y) : "l"(a));
    return r;
}

// ---------------- tree conv as gathered GEMM (packed f32x2 over h-pairs) ---
// out[b,h,j+1] = sum_{c,k} w[h,c,k] * T(in[b,c, idx[b,3j+k]]),  out[b,h,0]=0
// MODE 0: T = identity. MODE 1: T = relu((v-mean_b)*inv_b), mean/inv derived
// from raw {sum,sumsq} of the previous layer (fused layernorm).
// STATS 1: accumulate this layer's raw {sum,sumsq} into stats_out via atomics.
template<int CIN, int MODE, int STATS>
__global__ __launch_bounds__(256)
void conv_kernel(const float* __restrict__ in, const int* __restrict__ idxg,
                 const float* __restrict__ w, const float* __restrict__ bias,
                 const float* __restrict__ stats_in, float* __restrict__ stats_out,
                 float* __restrict__ out, int Hout)
{
    const int b   = blockIdx.y;
    const int h0  = blockIdx.x * 64;
    const int tid = threadIdx.x;
    const int nt  = tid & 31;   // lane: n within group (j = u*32 + nt)
    const int hg  = tid >> 5;   // warp: 8 h-groups of 8 h (4 packed pairs)
    const int K   = CIN * 3;

    __shared__ int   idx_s[384];
    __shared__ float data_s[8][128];
    __shared__ float g_s[24][128];
    __shared__ float w_s[24][64];
    __shared__ float red_s[16];

    float mean = 0.f, inv = 1.f;
    if (MODE == 1) {
        float s  = stats_in[2 * b];
        float s2 = stats_in[2 * b + 1];
        const float N = 65536.f;             // 512 * 128
        float m  = s / N;
        float var = (s2 - s * s / N) * (1.f / 65535.f);
        mean = m;
        inv  = 1.f / (sqrtf(fmaxf(var, 0.f)) + 1e-5f);
    }

    for (int i = tid; i < 384; i += 256) idx_s[i] = (i < N3) ? idxg[b * N3 + i] : 0;

    u64 acc[4][4];   // [h-pair][n-sub]
    #pragma unroll
    for (int p = 0; p < 4; p++)
        #pragma unroll
        for (int u = 0; u < 4; u++) acc[p][u] = 0ull;

    const float* inb = in + (size_t)b * CIN * 128;

    for (int c0 = 0; c0 < CIN; c0 += 8) {
        __syncthreads();   // previous GEMM step done before restaging
        // stage 8 input rows (apply fused norm+relu once per element)
        {
            int cl = tid >> 5, v = tid & 31;
            float4 d = *(const float4*)(inb + (size_t)(c0 + cl) * 128 + v * 4);
            if (MODE == 1) {
                d.x = fmaxf((d.x - mean) * inv, 0.f);
                d.y = fmaxf((d.y - mean) * inv, 0.f);
                d.z = fmaxf((d.z - mean) * inv, 0.f);
                d.w = fmaxf((d.w - mean) * inv, 0.f);
            }
            *(float4*)&data_s[cl][v * 4] = d;
        }
        // stage W tile transposed: w_s[kk][i]  (h contiguous -> packable pairs)
        #pragma unroll
        for (int e = tid; e < 24 * 64; e += 256) {
            int i = e / 24, kk = e % 24;
            w_s[kk][i] = w[(size_t)(h0 + i) * K + c0 * 3 + kk];
        }
        __syncthreads();
        // gather G tile: g_s[kk][j] = data_s[kk/3][idx[3j + kk%3]]
        #pragma unroll
        for (int e = tid; e < 24 * 128; e += 256) {
            int kk = e >> 7, j = e & 127;
            int c_l = kk / 3, k = kk - c_l * 3;
            g_s[kk][j] = (j < 127) ? data_s[c_l][idx_s[3 * j + k]] : 0.f;
        }
        __syncthreads();
        // packed register-blocked GEMM step
        #pragma unroll
        for (int kk = 0; kk < 24; kk++) {
            // weights come out of smem already packed as h-pairs (broadcast)
            ulonglong2 wA = *(const ulonglong2*)&w_s[kk][hg * 8];       // pairs (h0,h1),(h2,h3)
            ulonglong2 wB = *(const ulonglong2*)&w_s[kk][hg * 8 + 4];   // pairs (h4,h5),(h6,h7)
            float g0 = g_s[kk][0 * 32 + nt];
            float g1 = g_s[kk][1 * 32 + nt];
            float g2 = g_s[kk][2 * 32 + nt];
            float g3 = g_s[kk][3 * 32 + nt];
            u64 gp0 = rep2(g0), gp1 = rep2(g1), gp2 = rep2(g2), gp3 = rep2(g3);
            acc[0][0] = fma2(wA.x, gp0, acc[0][0]);
            acc[0][1] = fma2(wA.x, gp1, acc[0][1]);
            acc[0][2] = fma2(wA.x, gp2, acc[0][2]);
            acc[0][3] = fma2(wA.x, gp3, acc[0][3]);
            acc[1][0] = fma2(wA.y, gp0, acc[1][0]);
            acc[1][1] = fma2(wA.y, gp1, acc[1][1]);
            acc[1][2] = fma2(wA.y, gp2, acc[1][2]);
            acc[1][3] = fma2(wA.y, gp3, acc[1][3]);
            acc[2][0] = fma2(wB.x, gp0, acc[2][0]);
            acc[2][1] = fma2(wB.x, gp1, acc[2][1]);
            acc[2][2] = fma2(wB.x, gp2, acc[2][2]);
            acc[2][3] = fma2(wB.x, gp3, acc[2][3]);
            acc[3][0] = fma2(wB.y, gp0, acc[3][0]);
            acc[3][1] = fma2(wB.y, gp1, acc[3][1]);
            acc[3][2] = fma2(wB.y, gp2, acc[3][2]);
            acc[3][3] = fma2(wB.y, gp3, acc[3][3]);
        }
    }

    // epilogue: bias + coalesced store (+ fused stats partials)
    float* outb = out + (size_t)b * Hout * 128;
    float lsum = 0.f, lsq = 0.f;
    #pragma unroll
    for (int p = 0; p < 4; p++) {
        int hA = h0 + hg * 8 + 2 * p;
        float bbA = bias[hA], bbB = bias[hA + 1];
        #pragma unroll
        for (int u = 0; u < 4; u++) {
            int j = u * 32 + nt;
            float2 v = unpk(acc[p][u]);
            float vA = v.x + bbA, vB = v.y + bbB;
            if (j < 127) {
                outb[(size_t)hA * 128 + j + 1]       = vA;
                outb[(size_t)(hA + 1) * 128 + j + 1] = vB;
                if (STATS) { lsum += vA + vB; lsq += vA * vA + vB * vB; }
            }
        }
    }
    if (tid < 64) outb[(size_t)(h0 + tid) * 128] = 0.f;   // zero column

    if (STATS) {
        #pragma unroll
        for (int o = 16; o > 0; o >>= 1) {
            lsum += __shfl_xor_sync(0xffffffffu, lsum, o);
            lsq  += __shfl_xor_sync(0xffffffffu, lsq,  o);
        }
        if (nt == 0) { red_s[hg] = lsum; red_s[8 + hg] = lsq; }
        __syncthreads();
        if (tid == 0) {
            float a = 0.f, c = 0.f;
            #pragma unroll
            for (int i = 0; i < 8; i++) { a += red_s[i]; c += red_s[8 + i]; }
            atomicAdd(&stats_out[2 * b],     a);
            atomicAdd(&stats_out[2 * b + 1], c);
        }
    }
}

// ---------------- gate + softmax + attention pool + combined ----------------
#define GATE_SMEM_FLOATS (128 * 257 + 32 * 128 + 512 + 128 + 32)
__global__ __launch_bounds__(512, 1)
void gate_kernel(const float* __restrict__ emb, const float* __restrict__ gw1,
                 const float* __restrict__ gb1, const float* __restrict__ gw2,
                 const float* __restrict__ gb2, float* __restrict__ comb)
{
    extern __shared__ float sm[];
    float* et     = sm;                    // [128][257] : et[n][f]
    float* gw1c   = et + 128 * 257;        // [32][128]  : gw1c[fl][h]
    float* red    = gw1c + 32 * 128;       // [4][128]
    float* logits = red + 512;             // [128]
    float* rtmp   = logits + 128;          // [32]

    int b = blockIdx.x, tid = threadIdx.x;
    int n = tid & 127, hgrp = tid >> 7;    // hgrp 0..3
    const float* eb = emb + (size_t)b * 256 * 128;

    for (int e = tid; e < 256 * 128; e += 512) {
        int f = e >> 7, nn = e & 127;
        et[nn * 257 + f] = eb[e];
    }
    __syncthreads();

    float acc[32];
    #pragma unroll
    for (int s = 0; s < 32; s++) acc[s] = gb1[hgrp * 32 + s];

    for (int fc = 0; fc < 256; fc += 32) {
        for (int e = tid; e < 128 * 32; e += 512) {
            int h = e >> 5, fl = e & 31;
            gw1c[fl * 128 + h] = gw1[h * 256 + fc + fl];
        }
        __syncthreads();
        #pragma unroll 8
        for (int fl = 0; fl < 32; fl++) {
            float v = et[n * 257 + fc + fl];
            const float4* wp = (const float4*)&gw1c[fl * 128 + hgrp * 32];
            #pragma unroll
            for (int q = 0; q < 8; q++) {
                float4 w4 = wp[q];
                acc[q * 4 + 0] += v * w4.x;
                acc[q * 4 + 1] += v * w4.y;
                acc[q * 4 + 2] += v * w4.z;
                acc[q * 4 + 3] += v * w4.w;
            }
        }
        __syncthreads();
    }
    float p = 0.f;
    #pragma unroll
    for (int s = 0; s < 32; s++) p += fmaxf(acc[s], 0.f) * gw2[hgrp * 32 + s];
    red[hgrp * 128 + n] = p;
    __syncthreads();
    if (tid < 128)
        logits[tid] = red[tid] + red[128 + tid] + red[256 + tid] + red[384 + tid] + gb2[0];
    __syncthreads();
    if (tid < 128) {
        float v = logits[tid];
        for (int o = 16; o > 0; o >>= 1) v = fmaxf(v, __shfl_xor_sync(0xffffffffu, v, o));
        if ((tid & 31) == 0) rtmp[tid >> 5] = v;
    }
    __syncthreads();
    float gmax = fmaxf(fmaxf(rtmp[0], rtmp[1]), fmaxf(rtmp[2], rtmp[3]));
    if (tid < 128) logits[tid] = expf(logits[tid] - gmax);
    __syncthreads();
    if (tid < 128) {
        float v = logits[tid];
        for (int o = 16; o > 0; o >>= 1) v += __shfl_xor_sync(0xffffffffu, v, o);
        if ((tid & 31) == 0) rtmp[4 + (tid >> 5)] = v;
    }
    __syncthreads();
    float rinv = 1.f / (rtmp[4] + rtmp[5] + rtmp[6] + rtmp[7]);
    if (tid < 128) logits[tid] *= rinv;
    __syncthreads();
    if (tid < 256) {
        float pv = 0.f;
        #pragma unroll 8
        for (int nn = 0; nn < 128; nn++) pv += logits[nn] * et[nn * 257 + tid];
        comb[(size_t)b * 512 + tid]       = et[1 * 257 + tid];   // root = et[:,1,:]
        comb[(size_t)b * 512 + 256 + tid] = pv;                  // pool
    }
}

// ---------------- tiny MLP head: 512 -> 128 -> 64 -> 1 ----------------
__global__ __launch_bounds__(128)
void head_kernel(const float* __restrict__ comb,
                 const float* __restrict__ rw1, const float* __restrict__ rb1,
                 const float* __restrict__ rw2, const float* __restrict__ rb2,
                 const float* __restrict__ rw3, const float* __restrict__ rb3,
                 float* __restrict__ outv)
{
    __shared__ float cs[512];
    __shared__ float wc[128][33];
    __shared__ float h1[128];
    __shared__ float h2[64];
    int b = blockIdx.x, tid = threadIdx.x;

    for (int i = tid; i < 512; i += 128) cs[i] = comb[(size_t)b * 512 + i];

    float a = rb1[tid];
    for (int i0 = 0; i0 < 512; i0 += 32) {
        for (int e = tid; e < 128 * 32; e += 128) {
            int h = e >> 5, il = e & 31;
            wc[h][il] = rw1[h * 512 + i0 + il];
        }
        __syncthreads();
        #pragma unroll
        for (int il = 0; il < 32; il++) a += cs[i0 + il] * wc[tid][il];
        __syncthreads();
    }
    h1[tid] = fmaxf(a, 0.f);
    __syncthreads();

    float a2 = (tid < 64) ? rb2[tid] : 0.f;
    for (int i0 = 0; i0 < 128; i0 += 32) {
        for (int e = tid; e < 64 * 32; e += 128) {
            int h = e >> 5, il = e & 31;
            wc[h][il] = rw2[h * 128 + i0 + il];
        }
        __syncthreads();
        if (tid < 64) {
            #pragma unroll
            for (int il = 0; il < 32; il++) a2 += h1[i0 + il] * wc[tid][il];
        }
        __syncthreads();
    }
    if (tid < 64) h2[tid] = fmaxf(a2, 0.f);
    __syncthreads();

    if (tid < 64) {
        float p = h2[tid] * rw3[tid];
        for (int o = 16; o > 0; o >>= 1) p += __shfl_xor_sync(0xffffffffu, p, o);
        if ((tid & 31) == 0) h1[64 + (tid >> 5)] = p;
    }
    __syncthreads();
    if (tid == 0) outv[b] = h1[64] + h1[65] + rb3[0];
}

// ---------------- launch ----------------
extern "C" void kernel_launch(void* const* d_in, const int* in_sizes, int n_in,
                              void* d_out, int out_size)
{
    const float* trees = (const float*)d_in[0];
    const int*   idx   = (const int*)  d_in[1];
    const float* w1    = (const float*)d_in[2];
    const float* b1    = (const float*)d_in[3];
    const float* w2    = (const float*)d_in[4];
    const float* b2    = (const float*)d_in[5];
    const float* w3    = (const float*)d_in[6];
    const float* b3    = (const float*)d_in[7];
    const float* gw1   = (const float*)d_in[8];
    const float* gb1   = (const float*)d_in[9];
    const float* gw2   = (const float*)d_in[10];
    const float* gb2   = (const float*)d_in[11];
    const float* rw1   = (const float*)d_in[12];
    const float* rb1   = (const float*)d_in[13];
    const float* rw2   = (const float*)d_in[14];
    const float* rb2   = (const float*)d_in[15];
    const float* rw3   = (const float*)d_in[16];
    const float* rb3   = (const float*)d_in[17];

    float* out  = (float*)d_out;        // [512] final scores
    float* comb = out + 512;            // [512][512] combined

    float *x1, *x2, *embp, *st;
    cudaGetSymbolAddress((void**)&x1,   g_x1);
    cudaGetSymbolAddress((void**)&x2,   g_x2);
    cudaGetSymbolAddress((void**)&embp, g_emb);
    cudaGetSymbolAddress((void**)&st,   g_stats);
    float* st1 = st;
    float* st2 = st + 2 * BATCH;

    size_t gate_smem = (size_t)GATE_SMEM_FLOATS * sizeof(float);
    cudaFuncSetAttribute(gate_kernel, cudaFuncAttributeMaxDynamicSharedMemorySize,
                         (int)gate_smem);

    cudaMemsetAsync(st, 0, 4 * BATCH * sizeof(float));

    // layer 1: raw trees -> x1, accumulate stats1
    conv_kernel<200, 0, 1><<<dim3(8, BATCH), 256>>>(trees, idx, w1, b1, nullptr, st1, x1, 512);
    // layer 2: norm+relu(x1) -> x2, accumulate stats2
    conv_kernel<512, 1, 1><<<dim3(8, BATCH), 256>>>(x1, idx, w2, b2, st1, st2, x2, 512);
    // layer 3: norm+relu(x2) -> emb
    conv_kernel<512, 1, 0><<<dim3(4, BATCH), 256>>>(x2, idx, w3, b3, st2, nullptr, embp, 256);
    // attention pool + combined
    gate_kernel<<<BATCH, 512, gate_smem>>>(embp, gw1, gb1, gw2, gb2, comb);
    // MLP head
    head_kernel<<<BATCH, 128>>>(comb, rw1, rb1, rw2, rb2, rw3, rb3, out);
}

// round 3
// speedup vs baseline: 1.8068x; 1.7252x over previous
#include <cuda_runtime.h>
#include <math.h>

#define BATCH 512
typedef unsigned long long u64;
typedef unsigned int u32;

// ---------------- scratch (device globals: allocation-free) ----------------
__device__ float g_x1[(size_t)BATCH * 512 * 128];
__device__ float g_x2[(size_t)BATCH * 512 * 128];
__device__ float g_emb[(size_t)BATCH * 256 * 128];
__device__ float g_G[(size_t)BATCH * 1536 * 128];          // gathered activations
__device__ float g_wt[600 * 512 + 1536 * 512 + 1536 * 256]; // transposed weights
__device__ float g_stats[4 * BATCH];

// ---------------- packed fp32x2 helpers ----------------
__device__ __forceinline__ u64 fma2(u64 a, u64 b, u64 c) {
    u64 d;
    asm("fma.rn.f32x2 %0, %1, %2, %3;" : "=l"(d) : "l"(a), "l"(b), "l"(c));
    return d;
}
__device__ __forceinline__ u64 rep2(float x) {
    u64 d;
    asm("mov.b64 %0, {%1, %1};" : "=l"(d) : "f"(x));
    return d;
}
__device__ __forceinline__ float2 unpk(u64 a) {
    float2 r;
    asm("mov.b64 {%0, %1}, %2;" : "=f"(r.x), "=f"(r.y) : "l"(a));
    return r;
}
__device__ __forceinline__ void cpa16(u32 s, const float* g) {
    asm volatile("cp.async.cg.shared.global [%0], [%1], 16;" :: "r"(s), "l"(g));
}
#define CPA_COMMIT() asm volatile("cp.async.commit_group;")
template<int N> __device__ __forceinline__ void cpa_wait() {
    asm volatile("cp.async.wait_group %0;" :: "n"(N));
}

// ---------------- weight transpose: wt[k][h] = w[h][k] ----------------
__global__ void transpose_kernel(const float* __restrict__ w, float* __restrict__ wt,
                                 int H, int K)
{
    __shared__ float t[32][33];
    int bx = blockIdx.x * 32, by = blockIdx.y * 32;
    int x = bx + threadIdx.x, y = by + threadIdx.y;
    if (x < K && y < H) t[threadIdx.y][threadIdx.x] = w[(size_t)y * K + x];
    __syncthreads();
    int xo = by + threadIdx.x, yo = bx + threadIdx.y;
    if (xo < H && yo < K) wt[(size_t)yo * H + xo] = t[threadIdx.x][threadIdx.y];
}

// ---------------- gather (+ fused layernorm/relu of previous layer) ----------
// G[b][3c+k][j] = T(in[b][c][ idx[b][3j+k] ]) for j in 0..126, G[..][127]=0
template<int CCH, int MODE>
__global__ __launch_bounds__(256)
void gather_kernel(const float* __restrict__ in, const int* __restrict__ idxg,
                   const float* __restrict__ stats_in, float* __restrict__ G,
                   int CIN, int Ktot)
{
    const int b = blockIdx.y, c0 = blockIdx.x * CCH, tid = threadIdx.x;
    __shared__ int   idx_s[384];
    __shared__ float x_s[CCH * 128];

    float mean = 0.f, inv = 1.f;
    if (MODE == 1) {
        float s  = stats_in[2 * b];
        float s2 = stats_in[2 * b + 1];
        const float N = 65536.f;
        float m   = s / N;
        float var = (s2 - s * s / N) * (1.f / 65535.f);
        mean = m;
        inv  = 1.f / (sqrtf(fmaxf(var, 0.f)) + 1e-5f);
    }
    for (int i = tid; i < 384; i += 256) idx_s[i] = (i < 381) ? idxg[b * 381 + i] : 0;

    const float* inb = in + (size_t)b * CIN * 128 + (size_t)c0 * 128;
    for (int q = tid; q < CCH * 32; q += 256) {
        float4 v = *(const float4*)(inb + q * 4);
        if (MODE == 1) {
            v.x = fmaxf((v.x - mean) * inv, 0.f);
            v.y = fmaxf((v.y - mean) * inv, 0.f);
            v.z = fmaxf((v.z - mean) * inv, 0.f);
            v.w = fmaxf((v.w - mean) * inv, 0.f);
        }
        *(float4*)&x_s[q * 4] = v;
    }
    __syncthreads();

    float* Gb = G + (size_t)b * Ktot * 128 + (size_t)c0 * 3 * 128;
    for (int q = tid; q < CCH * 96; q += 256) {
        int kk = q >> 5, jq = q & 31;
        int c_l = kk / 3, km = kk - c_l * 3;
        const float* xr = &x_s[c_l * 128];
        int jb = jq * 4;
        float4 v;
        v.x = xr[idx_s[3 * jb + km]];
        v.y = xr[idx_s[3 * jb + 3 + km]];
        v.z = xr[idx_s[3 * jb + 6 + km]];
        v.w = (jb + 3 < 127) ? xr[idx_s[3 * jb + 9 + km]] : 0.f;
        *(float4*)(Gb + (size_t)kk * 128 + jb) = v;
    }
}

// ---------------- batched SGEMM: out[b][h][j+1] = sum_k wt[k][h]*G[b][k][j] --
// 128h x 128n block, 16h x 4n per thread, fp32x2 over h-pairs,
// cp.async double-buffered k-chunks of 24.
template<int K, int STATS>
__global__ __launch_bounds__(256, 2)
void gemm_kernel(const float* __restrict__ G, const float* __restrict__ wt,
                 const float* __restrict__ bias, float* __restrict__ stats_out,
                 float* __restrict__ out, int Hout)
{
    const int b = blockIdx.y, h0 = blockIdx.x * 128, tid = threadIdx.x;
    const int tx = tid & 31, ty = tid >> 5;
    __shared__ float w_s[2][24 * 132];
    __shared__ float g_s[2][24 * 132];
    __shared__ float red_s[16];

    const float* Gb = G + (size_t)b * K * 128;
    const int H = Hout;

    u32 w_sm[2], g_sm[2];
    w_sm[0] = (u32)__cvta_generic_to_shared(&w_s[0][0]);
    w_sm[1] = (u32)__cvta_generic_to_shared(&w_s[1][0]);
    g_sm[0] = (u32)__cvta_generic_to_shared(&g_s[0][0]);
    g_sm[1] = (u32)__cvta_generic_to_shared(&g_s[1][0]);

    u64 acc[8][4];
    #pragma unroll
    for (int p = 0; p < 8; p++)
        #pragma unroll
        for (int u = 0; u < 4; u++) acc[p][u] = 0ull;

    constexpr int NC = K / 24;

    // stage chunk c into buffer bufi (6 cp.async of 16B per thread)
    auto stage = [&](int c, int bufi) {
        int k0 = c * 24;
        #pragma unroll
        for (int i = 0; i < 3; i++) {
            int q  = tid + i * 256;
            int k  = q >> 5, hq = q & 31;
            u32 dst = (u32)((k * 132 + hq * 4) * 4);
            cpa16(w_sm[bufi] + dst, wt + (size_t)(k0 + k) * H + h0 + hq * 4);
            cpa16(g_sm[bufi] + dst, Gb + (size_t)(k0 + k) * 128 + hq * 4);
        }
        CPA_COMMIT();
    };

    stage(0, 0);
    for (int c = 0; c < NC; c++) {
        int bufi = c & 1;
        if (c + 1 < NC) { stage(c + 1, bufi ^ 1); cpa_wait<1>(); }
        else            { cpa_wait<0>(); }
        __syncthreads();
        const float* wsb = &w_s[bufi][0];
        const float* gsb = &g_s[bufi][0];
        #pragma unroll
        for (int k = 0; k < 24; k++) {
            const ulonglong2* wp = (const ulonglong2*)(wsb + k * 132 + ty * 16);
            ulonglong2 a0 = wp[0], a1 = wp[1], a2 = wp[2], a3 = wp[3];
            float4 g4 = *(const float4*)(gsb + k * 132 + tx * 4);
            u64 gp0 = rep2(g4.x), gp1 = rep2(g4.y), gp2 = rep2(g4.z), gp3 = rep2(g4.w);
            u64 wv[8] = {a0.x, a0.y, a1.x, a1.y, a2.x, a2.y, a3.x, a3.y};
            #pragma unroll
            for (int p = 0; p < 8; p++) {
                acc[p][0] = fma2(wv[p], gp0, acc[p][0]);
                acc[p][1] = fma2(wv[p], gp1, acc[p][1]);
                acc[p][2] = fma2(wv[p], gp2, acc[p][2]);
                acc[p][3] = fma2(wv[p], gp3, acc[p][3]);
            }
        }
        __syncthreads();
    }

    // epilogue: bias + store (cols 1..127), zero col 0, fused stats
    float* outb = out + (size_t)b * Hout * 128;
    float lsum = 0.f, lsq = 0.f;
    #pragma unroll
    for (int p = 0; p < 8; p++) {
        int hA = h0 + ty * 16 + 2 * p;
        float bbA = bias[hA], bbB = bias[hA + 1];
        #pragma unroll
        for (int u = 0; u < 4; u++) {
            int j = tx * 4 + u;
            float2 v = unpk(acc[p][u]);
            float va = v.x + bbA, vb = v.y + bbB;
            if (j < 127) {
                outb[(size_t)hA * 128 + j + 1]       = va;
                outb[(size_t)(hA + 1) * 128 + j + 1] = vb;
                if (STATS) { lsum += va + vb; lsq += va * va + vb * vb; }
            }
        }
    }
    if (tid < 128) outb[(size_t)(h0 + tid) * 128] = 0.f;

    if (STATS) {
        #pragma unroll
        for (int o = 16; o > 0; o >>= 1) {
            lsum += __shfl_xor_sync(0xffffffffu, lsum, o);
            lsq  += __shfl_xor_sync(0xffffffffu, lsq,  o);
        }
        if (tx == 0) { red_s[ty] = lsum; red_s[8 + ty] = lsq; }
        __syncthreads();
        if (tid == 0) {
            float a = 0.f, c2 = 0.f;
            #pragma unroll
            for (int i = 0; i < 8; i++) { a += red_s[i]; c2 += red_s[8 + i]; }
            atomicAdd(&stats_out[2 * b],     a);
            atomicAdd(&stats_out[2 * b + 1], c2);
        }
    }
}

// ---------------- gate + softmax + attention pool + combined ----------------
// outer-product gate1 GEMM: 128h x 128n, 8h x 4n per thread over f.
#define GATE_SMEM_FLOATS (256 * 132 + 32 * 130 + 16 * 128 + 128 + 8)
__global__ __launch_bounds__(512, 1)
void gate_kernel(const float* __restrict__ emb, const float* __restrict__ gw1,
                 const float* __restrict__ gb1, const float* __restrict__ gw2,
                 const float* __restrict__ gb2, float* __restrict__ comb)
{
    extern __shared__ float sm[];
    float* et     = sm;                    // [256][132] f-major
    float* wc     = et + 256 * 132;        // [32][130]  wc[fl][h]
    float* red    = wc + 32 * 130;         // [16][128]
    float* logits = red + 16 * 128;        // [128]
    float* rtmp   = logits + 128;          // [8]

    int b = blockIdx.x, tid = threadIdx.x;
    int tx = tid & 31, ty = tid >> 5;      // ty 0..15 (8h each), tx: 4n each
    const float* eb = emb + (size_t)b * 256 * 128;

    for (int q = tid; q < 8192; q += 512) {
        int f = q >> 5, nq = q & 31;
        float4 v = *(const float4*)(eb + f * 128 + nq * 4);
        *(float4*)&et[f * 132 + nq * 4] = v;
    }

    u64 acc[4][4];
    const u64* gb1p = (const u64*)gb1;
    #pragma unroll
    for (int p = 0; p < 4; p++) {
        u64 bp = gb1p[ty * 4 + p];
        #pragma unroll
        for (int u = 0; u < 4; u++) acc[p][u] = bp;
    }
    __syncthreads();

    for (int fc = 0; fc < 256; fc += 32) {
        for (int q = tid; q < 1024; q += 512) {
            int h = q >> 3, flq = q & 7;
            float4 v = *(const float4*)(gw1 + h * 256 + fc + flq * 4);
            wc[(flq * 4 + 0) * 130 + h] = v.x;
            wc[(flq * 4 + 1) * 130 + h] = v.y;
            wc[(flq * 4 + 2) * 130 + h] = v.z;
            wc[(flq * 4 + 3) * 130 + h] = v.w;
        }
        __syncthreads();
        #pragma unroll 4
        for (int fl = 0; fl < 32; fl++) {
            const u64* wp = (const u64*)&wc[fl * 130 + ty * 8];
            u64 w0 = wp[0], w1 = wp[1], w2v = wp[2], w3v = wp[3];
            float4 g4 = *(const float4*)&et[(fc + fl) * 132 + tx * 4];
            u64 gp0 = rep2(g4.x), gp1 = rep2(g4.y), gp2 = rep2(g4.z), gp3 = rep2(g4.w);
            u64 wv[4] = {w0, w1, w2v, w3v};
            #pragma unroll
            for (int p = 0; p < 4; p++) {
                acc[p][0] = fma2(wv[p], gp0, acc[p][0]);
                acc[p][1] = fma2(wv[p], gp1, acc[p][1]);
                acc[p][2] = fma2(wv[p], gp2, acc[p][2]);
                acc[p][3] = fma2(wv[p], gp3, acc[p][3]);
            }
        }
        __syncthreads();
    }

    // gate2 partials: relu(gate1) . gw2
    const u64* gw2p = (const u64*)gw2;
    float part[4] = {0.f, 0.f, 0.f, 0.f};
    #pragma unroll
    for (int p = 0; p < 4; p++) {
        float2 wv = unpk(gw2p[ty * 4 + p]);
        #pragma unroll
        for (int u = 0; u < 4; u++) {
            float2 v = unpk(acc[p][u]);
            part[u] += fmaxf(v.x, 0.f) * wv.x + fmaxf(v.y, 0.f) * wv.y;
        }
    }
    #pragma unroll
    for (int u = 0; u < 4; u++) red[ty * 128 + tx * 4 + u] = part[u];
    __syncthreads();

    if (tid < 128) {
        float s = gb2[0];
        #pragma unroll
        for (int t = 0; t < 16; t++) s += red[t * 128 + tid];
        logits[tid] = s;
    }
    __syncthreads();
    if (tid < 128) {
        float v = logits[tid];
        for (int o = 16; o > 0; o >>= 1) v = fmaxf(v, __shfl_xor_sync(0xffffffffu, v, o));
        if ((tid & 31) == 0) rtmp[tid >> 5] = v;
    }
    __syncthreads();
    float gmax = fmaxf(fmaxf(rtmp[0], rtmp[1]), fmaxf(rtmp[2], rtmp[3]));
    if (tid < 128) logits[tid] = expf(logits[tid] - gmax);
    __syncthreads();
    if (tid < 128) {
        float v = logits[tid];
        for (int o = 16; o > 0; o >>= 1) v += __shfl_xor_sync(0xffffffffu, v, o);
        if ((tid & 31) == 0) rtmp[4 + (tid >> 5)] = v;
    }
    __syncthreads();
    float rinv = 1.f / (rtmp[4] + rtmp[5] + rtmp[6] + rtmp[7]);
    if (tid < 128) logits[tid] *= rinv;
    __syncthreads();

    if (tid < 256) {
        int f = tid;
        float pv = 0.f;
        #pragma unroll 8
        for (int n = 0; n < 128; n++) pv += logits[n] * et[f * 132 + n];
        comb[(size_t)b * 512 + f]       = et[f * 132 + 1];   // root = et[:,1,:]
        comb[(size_t)b * 512 + 256 + f] = pv;                // pool
    }
}

// ---------------- tiny MLP head: 512 -> 128 -> 64 -> 1 ----------------
__global__ __launch_bounds__(128)
void head_kernel(const float* __restrict__ comb,
                 const float* __restrict__ rw1, const float* __restrict__ rb1,
                 const float* __restrict__ rw2, const float* __restrict__ rb2,
                 const float* __restrict__ rw3, const float* __restrict__ rb3,
                 float* __restrict__ outv)
{
    __shared__ float cs[512];
    __shared__ float wcs[128][33];
    __shared__ float h1[128];
    __shared__ float h2[64];
    int b = blockIdx.x, tid = threadIdx.x;

    for (int i = tid; i < 512; i += 128) cs[i] = comb[(size_t)b * 512 + i];

    float a = rb1[tid];
    for (int i0 = 0; i0 < 512; i0 += 32) {
        for (int e = tid; e < 128 * 32; e += 128) {
            int h = e >> 5, il = e & 31;
            wcs[h][il] = rw1[h * 512 + i0 + il];
        }
        __syncthreads();
        #pragma unroll
        for (int il = 0; il < 32; il++) a += cs[i0 + il] * wcs[tid][il];
        __syncthreads();
    }
    h1[tid] = fmaxf(a, 0.f);
    __syncthreads();

    float a2 = (tid < 64) ? rb2[tid] : 0.f;
    for (int i0 = 0; i0 < 128; i0 += 32) {
        for (int e = tid; e < 64 * 32; e += 128) {
            int h = e >> 5, il = e & 31;
            wcs[h][il] = rw2[h * 128 + i0 + il];
        }
        __syncthreads();
        if (tid < 64) {
            #pragma unroll
            for (int il = 0; il < 32; il++) a2 += h1[i0 + il] * wcs[tid][il];
        }
        __syncthreads();
    }
    if (tid < 64) h2[tid] = fmaxf(a2, 0.f);
    __syncthreads();

    if (tid < 64) {
        float p = h2[tid] * rw3[tid];
        for (int o = 16; o > 0; o >>= 1) p += __shfl_xor_sync(0xffffffffu, p, o);
        if ((tid & 31) == 0) h1[64 + (tid >> 5)] = p;
    }
    __syncthreads();
    if (tid == 0) outv[b] = h1[64] + h1[65] + rb3[0];
}

// ---------------- launch ----------------
extern "C" void kernel_launch(void* const* d_in, const int* in_sizes, int n_in,
                              void* d_out, int out_size)
{
    const float* trees = (const float*)d_in[0];
    const int*   idx   = (const int*)  d_in[1];
    const float* w1    = (const float*)d_in[2];
    const float* b1    = (const float*)d_in[3];
    const float* w2    = (const float*)d_in[4];
    const float* b2    = (const float*)d_in[5];
    const float* w3    = (const float*)d_in[6];
    const float* b3    = (const float*)d_in[7];
    const float* gw1   = (const float*)d_in[8];
    const float* gb1   = (const float*)d_in[9];
    const float* gw2   = (const float*)d_in[10];
    const float* gb2   = (const float*)d_in[11];
    const float* rw1   = (const float*)d_in[12];
    const float* rb1   = (const float*)d_in[13];
    const float* rw2   = (const float*)d_in[14];
    const float* rb2   = (const float*)d_in[15];
    const float* rw3   = (const float*)d_in[16];
    const float* rb3   = (const float*)d_in[17];

    float* out  = (float*)d_out;        // [512] final scores
    float* comb = out + 512;            // [512][512] combined

    float *x1, *x2, *embp, *G, *wt, *st;
    cudaGetSymbolAddress((void**)&x1,   g_x1);
    cudaGetSymbolAddress((void**)&x2,   g_x2);
    cudaGetSymbolAddress((void**)&embp, g_emb);
    cudaGetSymbolAddress((void**)&G,    g_G);
    cudaGetSymbolAddress((void**)&wt,   g_wt);
    cudaGetSymbolAddress((void**)&st,   g_stats);
    float* wt1 = wt;
    float* wt2 = wt1 + 600 * 512;
    float* wt3 = wt2 + 1536 * 512;
    float* st1 = st;
    float* st2 = st + 2 * BATCH;

    size_t gate_smem = (size_t)GATE_SMEM_FLOATS * sizeof(float);
    cudaFuncSetAttribute(gate_kernel, cudaFuncAttributeMaxDynamicSharedMemorySize,
                         (int)gate_smem);

    cudaMemsetAsync(st, 0, 4 * BATCH * sizeof(float));

    transpose_kernel<<<dim3(19, 16), dim3(32, 32)>>>(w1, wt1, 512, 600);
    transpose_kernel<<<dim3(48, 16), dim3(32, 32)>>>(w2, wt2, 512, 1536);
    transpose_kernel<<<dim3(48,  8), dim3(32, 32)>>>(w3, wt3, 256, 1536);

    // layer 1
    gather_kernel<40, 0><<<dim3(5, BATCH), 256>>>(trees, idx, nullptr, G, 200, 600);
    gemm_kernel<600, 1><<<dim3(4, BATCH), 256>>>(G, wt1, b1, st1, x1, 512);
    // layer 2
    gather_kernel<64, 1><<<dim3(8, BATCH), 256>>>(x1, idx, st1, G, 512, 1536);
    gemm_kernel<1536, 1><<<dim3(4, BATCH), 256>>>(G, wt2, b2, st2, x2, 512);
    // layer 3
    gather_kernel<64, 1><<<dim3(8, BATCH), 256>>>(x2, idx, st2, G, 512, 1536);
    gemm_kernel<1536, 0><<<dim3(2, BATCH), 256>>>(G, wt3, b3, nullptr, embp, 256);
    // attention pool + combined
    gate_kernel<<<BATCH, 512, gate_smem>>>(embp, gw1, gb1, gw2, gb2, comb);
    // MLP head
    head_kernel<<<BATCH, 128>>>(comb, rw1, rb1, rw2, rb2, rw3, rb3, out);
}

// round 4
// speedup vs baseline: 1.8073x; 1.0003x over previous
#include <cuda_runtime.h>
#include <math.h>

#define BATCH 512
typedef unsigned long long u64;
typedef unsigned int u32;

// ---------------- scratch (device globals: allocation-free) ----------------
__device__ float g_x1[(size_t)BATCH * 512 * 128];
__device__ float g_x2[(size_t)BATCH * 512 * 128];
__device__ float g_emb[(size_t)BATCH * 256 * 128];
__device__ float g_G[(size_t)BATCH * 1536 * 128];          // gathered activations
__device__ float g_wt[600 * 512 + 1536 * 512 + 1536 * 256]; // transposed weights
__device__ float g_stats[4 * BATCH];

// ---------------- packed fp32x2 helpers ----------------
__device__ __forceinline__ u64 fma2(u64 a, u64 b, u64 c) {
    u64 d;
    asm("fma.rn.f32x2 %0, %1, %2, %3;" : "=l"(d) : "l"(a), "l"(b), "l"(c));
    return d;
}
__device__ __forceinline__ u64 rep2(float x) {
    u64 d;
    asm("mov.b64 %0, {%1, %1};" : "=l"(d) : "f"(x));
    return d;
}
__device__ __forceinline__ float2 unpk(u64 a) {
    float2 r;
    asm("mov.b64 {%0, %1}, %2;" : "=f"(r.x), "=f"(r.y) : "l"(a));
    return r;
}
__device__ __forceinline__ void cpa16(u32 s, const float* g) {
    asm volatile("cp.async.cg.shared.global [%0], [%1], 16;" :: "r"(s), "l"(g));
}
#define CPA_COMMIT() asm volatile("cp.async.commit_group;")
template<int N> __device__ __forceinline__ void cpa_wait() {
    asm volatile("cp.async.wait_group %0;" :: "n"(N));
}

// ---------------- weight transpose: wt[k][h] = w[h][k] ----------------
__global__ void transpose_kernel(const float* __restrict__ w, float* __restrict__ wt,
                                 int H, int K)
{
    __shared__ float t[32][33];
    int bx = blockIdx.x * 32, by = blockIdx.y * 32;
    int x = bx + threadIdx.x, y = by + threadIdx.y;
    if (x < K && y < H) t[threadIdx.y][threadIdx.x] = w[(size_t)y * K + x];
    __syncthreads();
    int xo = by + threadIdx.x, yo = bx + threadIdx.y;
    if (xo < H && yo < K) wt[(size_t)yo * H + xo] = t[threadIdx.x][threadIdx.y];
}

// ---------------- gather (+ fused layernorm/relu of previous layer) ----------
// G[b][3c+k][j] = T(in[b][c][ idx[b][3j+k] ]) for j in 0..126, G[..][127]=0
template<int CCH, int MODE>
__global__ __launch_bounds__(256)
void gather_kernel(const float* __restrict__ in, const int* __restrict__ idxg,
                   const float* __restrict__ stats_in, float* __restrict__ G,
                   int CIN, int Ktot)
{
    const int b = blockIdx.y, c0 = blockIdx.x * CCH, tid = threadIdx.x;
    __shared__ int   idx_s[384];
    __shared__ float x_s[CCH * 128];

    float mean = 0.f, inv = 1.f;
    if (MODE == 1) {
        float s  = stats_in[2 * b];
        float s2 = stats_in[2 * b + 1];
        const float N = 65536.f;
        float m   = s / N;
        float var = (s2 - s * s / N) * (1.f / 65535.f);
        mean = m;
        inv  = 1.f / (sqrtf(fmaxf(var, 0.f)) + 1e-5f);
    }
    for (int i = tid; i < 384; i += 256) idx_s[i] = (i < 381) ? idxg[b * 381 + i] : 0;

    const float* inb = in + (size_t)b * CIN * 128 + (size_t)c0 * 128;
    for (int q = tid; q < CCH * 32; q += 256) {
        float4 v = *(const float4*)(inb + q * 4);
        if (MODE == 1) {
            v.x = fmaxf((v.x - mean) * inv, 0.f);
            v.y = fmaxf((v.y - mean) * inv, 0.f);
            v.z = fmaxf((v.z - mean) * inv, 0.f);
            v.w = fmaxf((v.w - mean) * inv, 0.f);
        }
        *(float4*)&x_s[q * 4] = v;
    }
    __syncthreads();

    float* Gb = G + (size_t)b * Ktot * 128 + (size_t)c0 * 3 * 128;
    for (int q = tid; q < CCH * 96; q += 256) {
        int kk = q >> 5, jq = q & 31;
        int c_l = kk / 3, km = kk - c_l * 3;
        const float* xr = &x_s[c_l * 128];
        int jb = jq * 4;
        float4 v;
        v.x = xr[idx_s[3 * jb + km]];
        v.y = xr[idx_s[3 * jb + 3 + km]];
        v.z = xr[idx_s[3 * jb + 6 + km]];
        v.w = (jb + 3 < 127) ? xr[idx_s[3 * jb + 9 + km]] : 0.f;
        *(float4*)(Gb + (size_t)kk * 128 + jb) = v;
    }
}

// ---------------- batched SGEMM: out[b][h][j+1] = sum_k wt[k][h]*G[b][k][j] --
// 128h x 128n block, 16h x 4n per thread, fp32x2 over h-pairs,
// cp.async double-buffered k-chunks of 24.
template<int K, int STATS>
__global__ __launch_bounds__(256, 2)
void gemm_kernel(const float* __restrict__ G, const float* __restrict__ wt,
                 const float* __restrict__ bias, float* __restrict__ stats_out,
                 float* __restrict__ out, int Hout)
{
    const int b = blockIdx.y, h0 = blockIdx.x * 128, tid = threadIdx.x;
    const int tx = tid & 31, ty = tid >> 5;
    __shared__ float w_s[2][24 * 132];
    __shared__ float g_s[2][24 * 132];
    __shared__ float red_s[16];

    const float* Gb = G + (size_t)b * K * 128;
    const int H = Hout;

    u32 w_sm[2], g_sm[2];
    w_sm[0] = (u32)__cvta_generic_to_shared(&w_s[0][0]);
    w_sm[1] = (u32)__cvta_generic_to_shared(&w_s[1][0]);
    g_sm[0] = (u32)__cvta_generic_to_shared(&g_s[0][0]);
    g_sm[1] = (u32)__cvta_generic_to_shared(&g_s[1][0]);

    u64 acc[8][4];
    #pragma unroll
    for (int p = 0; p < 8; p++)
        #pragma unroll
        for (int u = 0; u < 4; u++) acc[p][u] = 0ull;

    constexpr int NC = K / 24;

    // stage chunk c into buffer bufi (6 cp.async of 16B per thread)
    auto stage = [&](int c, int bufi) {
        int k0 = c * 24;
        #pragma unroll
        for (int i = 0; i < 3; i++) {
            int q  = tid + i * 256;
            int k  = q >> 5, hq = q & 31;
            u32 dst = (u32)((k * 132 + hq * 4) * 4);
            cpa16(w_sm[bufi] + dst, wt + (size_t)(k0 + k) * H + h0 + hq * 4);
            cpa16(g_sm[bufi] + dst, Gb + (size_t)(k0 + k) * 128 + hq * 4);
        }
        CPA_COMMIT();
    };

    stage(0, 0);
    for (int c = 0; c < NC; c++) {
        int bufi = c & 1;
        if (c + 1 < NC) { stage(c + 1, bufi ^ 1); cpa_wait<1>(); }
        else            { cpa_wait<0>(); }
        __syncthreads();
        const float* wsb = &w_s[bufi][0];
        const float* gsb = &g_s[bufi][0];
        #pragma unroll
        for (int k = 0; k < 24; k++) {
            const ulonglong2* wp = (const ulonglong2*)(wsb + k * 132 + ty * 16);
            ulonglong2 a0 = wp[0], a1 = wp[1], a2 = wp[2], a3 = wp[3];
            float4 g4 = *(const float4*)(gsb + k * 132 + tx * 4);
            u64 gp0 = rep2(g4.x), gp1 = rep2(g4.y), gp2 = rep2(g4.z), gp3 = rep2(g4.w);
            u64 wv[8] = {a0.x, a0.y, a1.x, a1.y, a2.x, a2.y, a3.x, a3.y};
            #pragma unroll
            for (int p = 0; p < 8; p++) {
                acc[p][0] = fma2(wv[p], gp0, acc[p][0]);
                acc[p][1] = fma2(wv[p], gp1, acc[p][1]);
                acc[p][2] = fma2(wv[p], gp2, acc[p][2]);
                acc[p][3] = fma2(wv[p], gp3, acc[p][3]);
            }
        }
        __syncthreads();
    }

    // epilogue: bias + store (cols 1..127), zero col 0, fused stats
    float* outb = out + (size_t)b * Hout * 128;
    float lsum = 0.f, lsq = 0.f;
    #pragma unroll
    for (int p = 0; p < 8; p++) {
        int hA = h0 + ty * 16 + 2 * p;
        float bbA = bias[hA], bbB = bias[hA + 1];
        #pragma unroll
        for (int u = 0; u < 4; u++) {
            int j = tx * 4 + u;
            float2 v = unpk(acc[p][u]);
            float va = v.x + bbA, vb = v.y + bbB;
            if (j < 127) {
                outb[(size_t)hA * 128 + j + 1]       = va;
                outb[(size_t)(hA + 1) * 128 + j + 1] = vb;
                if (STATS) { lsum += va + vb; lsq += va * va + vb * vb; }
            }
        }
    }
    if (tid < 128) outb[(size_t)(h0 + tid) * 128] = 0.f;

    if (STATS) {
        #pragma unroll
        for (int o = 16; o > 0; o >>= 1) {
            lsum += __shfl_xor_sync(0xffffffffu, lsum, o);
            lsq  += __shfl_xor_sync(0xffffffffu, lsq,  o);
        }
        if (tx == 0) { red_s[ty] = lsum; red_s[8 + ty] = lsq; }
        __syncthreads();
        if (tid == 0) {
            float a = 0.f, c2 = 0.f;
            #pragma unroll
            for (int i = 0; i < 8; i++) { a += red_s[i]; c2 += red_s[8 + i]; }
            atomicAdd(&stats_out[2 * b],     a);
            atomicAdd(&stats_out[2 * b + 1], c2);
        }
    }
}

// ---------------- gate + softmax + attention pool + combined ----------------
// outer-product gate1 GEMM: 128h x 128n, 8h x 4n per thread over f.
#define GATE_SMEM_FLOATS (256 * 132 + 32 * 130 + 16 * 128 + 128 + 8)
__global__ __launch_bounds__(512, 1)
void gate_kernel(const float* __restrict__ emb, const float* __restrict__ gw1,
                 const float* __restrict__ gb1, const float* __restrict__ gw2,
                 const float* __restrict__ gb2, float* __restrict__ comb)
{
    extern __shared__ float sm[];
    float* et     = sm;                    // [256][132] f-major
    float* wc     = et + 256 * 132;        // [32][130]  wc[fl][h]
    float* red    = wc + 32 * 130;         // [16][128]
    float* logits = red + 16 * 128;        // [128]
    float* rtmp   = logits + 128;          // [8]

    int b = blockIdx.x, tid = threadIdx.x;
    int tx = tid & 31, ty = tid >> 5;      // ty 0..15 (8h each), tx: 4n each
    const float* eb = emb + (size_t)b * 256 * 128;

    for (int q = tid; q < 8192; q += 512) {
        int f = q >> 5, nq = q & 31;
        float4 v = *(const float4*)(eb + f * 128 + nq * 4);
        *(float4*)&et[f * 132 + nq * 4] = v;
    }

    u64 acc[4][4];
    const u64* gb1p = (const u64*)gb1;
    #pragma unroll
    for (int p = 0; p < 4; p++) {
        u64 bp = gb1p[ty * 4 + p];
        #pragma unroll
        for (int u = 0; u < 4; u++) acc[p][u] = bp;
    }
    __syncthreads();

    for (int fc = 0; fc < 256; fc += 32) {
        for (int q = tid; q < 1024; q += 512) {
            int h = q >> 3, flq = q & 7;
            float4 v = *(const float4*)(gw1 + h * 256 + fc + flq * 4);
            wc[(flq * 4 + 0) * 130 + h] = v.x;
            wc[(flq * 4 + 1) * 130 + h] = v.y;
            wc[(flq * 4 + 2) * 130 + h] = v.z;
            wc[(flq * 4 + 3) * 130 + h] = v.w;
        }
        __syncthreads();
        #pragma unroll 4
        for (int fl = 0; fl < 32; fl++) {
            const u64* wp = (const u64*)&wc[fl * 130 + ty * 8];
            u64 w0 = wp[0], w1 = wp[1], w2v = wp[2], w3v = wp[3];
            float4 g4 = *(const float4*)&et[(fc + fl) * 132 + tx * 4];
            u64 gp0 = rep2(g4.x), gp1 = rep2(g4.y), gp2 = rep2(g4.z), gp3 = rep2(g4.w);
            u64 wv[4] = {w0, w1, w2v, w3v};
            #pragma unroll
            for (int p = 0; p < 4; p++) {
                acc[p][0] = fma2(wv[p], gp0, acc[p][0]);
                acc[p][1] = fma2(wv[p], gp1, acc[p][1]);
                acc[p][2] = fma2(wv[p], gp2, acc[p][2]);
                acc[p][3] = fma2(wv[p], gp3, acc[p][3]);
            }
        }
        __syncthreads();
    }

    // gate2 partials: relu(gate1) . gw2
    const u64* gw2p = (const u64*)gw2;
    float part[4] = {0.f, 0.f, 0.f, 0.f};
    #pragma unroll
    for (int p = 0; p < 4; p++) {
        float2 wv = unpk(gw2p[ty * 4 + p]);
        #pragma unroll
        for (int u = 0; u < 4; u++) {
            float2 v = unpk(acc[p][u]);
            part[u] += fmaxf(v.x, 0.f) * wv.x + fmaxf(v.y, 0.f) * wv.y;
        }
    }
    #pragma unroll
    for (int u = 0; u < 4; u++) red[ty * 128 + tx * 4 + u] = part[u];
    __syncthreads();

    if (tid < 128) {
        float s = gb2[0];
        #pragma unroll
        for (int t = 0; t < 16; t++) s += red[t * 128 + tid];
        logits[tid] = s;
    }
    __syncthreads();
    if (tid < 128) {
        float v = logits[tid];
        for (int o = 16; o > 0; o >>= 1) v = fmaxf(v, __shfl_xor_sync(0xffffffffu, v, o));
        if ((tid & 31) == 0) rtmp[tid >> 5] = v;
    }
    __syncthreads();
    float gmax = fmaxf(fmaxf(rtmp[0], rtmp[1]), fmaxf(rtmp[2], rtmp[3]));
    if (tid < 128) logits[tid] = expf(logits[tid] - gmax);
    __syncthreads();
    if (tid < 128) {
        float v = logits[tid];
        for (int o = 16; o > 0; o >>= 1) v += __shfl_xor_sync(0xffffffffu, v, o);
        if ((tid & 31) == 0) rtmp[4 + (tid >> 5)] = v;
    }
    __syncthreads();
    float rinv = 1.f / (rtmp[4] + rtmp[5] + rtmp[6] + rtmp[7]);
    if (tid < 128) logits[tid] *= rinv;
    __syncthreads();

    if (tid < 256) {
        int f = tid;
        float pv = 0.f;
        #pragma unroll 8
        for (int n = 0; n < 128; n++) pv += logits[n] * et[f * 132 + n];
        comb[(size_t)b * 512 + f]       = et[f * 132 + 1];   // root = et[:,1,:]
        comb[(size_t)b * 512 + 256 + f] = pv;                // pool
    }
}

// ---------------- tiny MLP head: 512 -> 128 -> 64 -> 1 ----------------
__global__ __launch_bounds__(128)
void head_kernel(const float* __restrict__ comb,
                 const float* __restrict__ rw1, const float* __restrict__ rb1,
                 const float* __restrict__ rw2, const float* __restrict__ rb2,
                 const float* __restrict__ rw3, const float* __restrict__ rb3,
                 float* __restrict__ outv)
{
    __shared__ float cs[512];
    __shared__ float wcs[128][33];
    __shared__ float h1[128];
    __shared__ float h2[64];
    int b = blockIdx.x, tid = threadIdx.x;

    for (int i = tid; i < 512; i += 128) cs[i] = comb[(size_t)b * 512 + i];

    float a = rb1[tid];
    for (int i0 = 0; i0 < 512; i0 += 32) {
        for (int e = tid; e < 128 * 32; e += 128) {
            int h = e >> 5, il = e & 31;
            wcs[h][il] = rw1[h * 512 + i0 + il];
        }
        __syncthreads();
        #pragma unroll
        for (int il = 0; il < 32; il++) a += cs[i0 + il] * wcs[tid][il];
        __syncthreads();
    }
    h1[tid] = fmaxf(a, 0.f);
    __syncthreads();

    float a2 = (tid < 64) ? rb2[tid] : 0.f;
    for (int i0 = 0; i0 < 128; i0 += 32) {
        for (int e = tid; e < 64 * 32; e += 128) {
            int h = e >> 5, il = e & 31;
            wcs[h][il] = rw2[h * 128 + i0 + il];
        }
        __syncthreads();
        if (tid < 64) {
            #pragma unroll
            for (int il = 0; il < 32; il++) a2 += h1[i0 + il] * wcs[tid][il];
        }
        __syncthreads();
    }
    if (tid < 64) h2[tid] = fmaxf(a2, 0.f);
    __syncthreads();

    if (tid < 64) {
        float p = h2[tid] * rw3[tid];
        for (int o = 16; o > 0; o >>= 1) p += __shfl_xor_sync(0xffffffffu, p, o);
        if ((tid & 31) == 0) h1[64 + (tid >> 5)] = p;
    }
    __syncthreads();
    if (tid == 0) outv[b] = h1[64] + h1[65] + rb3[0];
}

// ---------------- launch ----------------
extern "C" void kernel_launch(void* const* d_in, const int* in_sizes, int n_in,
                              void* d_out, int out_size)
{
    const float* trees = (const float*)d_in[0];
    const int*   idx   = (const int*)  d_in[1];
    const float* w1    = (const float*)d_in[2];
    const float* b1    = (const float*)d_in[3];
    const float* w2    = (const float*)d_in[4];
    const float* b2    = (const float*)d_in[5];
    const float* w3    = (const float*)d_in[6];
    const float* b3    = (const float*)d_in[7];
    const float* gw1   = (const float*)d_in[8];
    const float* gb1   = (const float*)d_in[9];
    const float* gw2   = (const float*)d_in[10];
    const float* gb2   = (const float*)d_in[11];
    const float* rw1   = (const float*)d_in[12];
    const float* rb1   = (const float*)d_in[13];
    const float* rw2   = (const float*)d_in[14];
    const float* rb2   = (const float*)d_in[15];
    const float* rw3   = (const float*)d_in[16];
    const float* rb3   = (const float*)d_in[17];

    float* out  = (float*)d_out;        // [512] final scores
    float* comb = out + 512;            // [512][512] combined

    float *x1, *x2, *embp, *G, *wt, *st;
    cudaGetSymbolAddress((void**)&x1,   g_x1);
    cudaGetSymbolAddress((void**)&x2,   g_x2);
    cudaGetSymbolAddress((void**)&embp, g_emb);
    cudaGetSymbolAddress((void**)&G,    g_G);
    cudaGetSymbolAddress((void**)&wt,   g_wt);
    cudaGetSymbolAddress((void**)&st,   g_stats);
    float* wt1 = wt;
    float* wt2 = wt1 + 600 * 512;
    float* wt3 = wt2 + 1536 * 512;
    float* st1 = st;
    float* st2 = st + 2 * BATCH;

    size_t gate_smem = (size_t)GATE_SMEM_FLOATS * sizeof(float);
    cudaFuncSetAttribute(gate_kernel, cudaFuncAttributeMaxDynamicSharedMemorySize,
                         (int)gate_smem);

    cudaMemsetAsync(st, 0, 4 * BATCH * sizeof(float));

    transpose_kernel<<<dim3(19, 16), dim3(32, 32)>>>(w1, wt1, 512, 600);
    transpose_kernel<<<dim3(48, 16), dim3(32, 32)>>>(w2, wt2, 512, 1536);
    transpose_kernel<<<dim3(48,  8), dim3(32, 32)>>>(w3, wt3, 256, 1536);

    // layer 1
    gather_kernel<40, 0><<<dim3(5, BATCH), 256>>>(trees, idx, nullptr, G, 200, 600);
    gemm_kernel<600, 1><<<dim3(4, BATCH), 256>>>(G, wt1, b1, st1, x1, 512);
    // layer 2
    gather_kernel<64, 1><<<dim3(8, BATCH), 256>>>(x1, idx, st1, G, 512, 1536);
    gemm_kernel<1536, 1><<<dim3(4, BATCH), 256>>>(G, wt2, b2, st2, x2, 512);
    // layer 3
    gather_kernel<64, 1><<<dim3(8, BATCH), 256>>>(x2, idx, st2, G, 512, 1536);
    gemm_kernel<1536, 0><<<dim3(2, BATCH), 256>>>(G, wt3, b3, nullptr, embp, 256);
    // attention pool + combined
    gate_kernel<<<BATCH, 512, gate_smem>>>(embp, gw1, gb1, gw2, gb2, comb);
    // MLP head
    head_kernel<<<BATCH, 128>>>(comb, rw1, rb1, rw2, rb2, rw3, rb3, out);
}

// round 6
// speedup vs baseline: 2.5349x; 1.4026x over previous
#include <cuda_runtime.h>
#include <cuda_bf16.h>
#include <math.h>
#include <stdint.h>

#define BATCH 512
#define NTOT  65536
typedef unsigned long long u64;
typedef unsigned int u32;

// ---------------- scratch (device globals) ----------------
__device__ __nv_bfloat16 g_Ghi[(size_t)NTOT * 1536];
__device__ __nv_bfloat16 g_Glo[(size_t)NTOT * 1536];
__device__ __nv_bfloat16 g_Whi[512 * 640 + 512 * 1536 + 256 * 1536];
__device__ __nv_bfloat16 g_Wlo[512 * 640 + 512 * 1536 + 256 * 1536];
__device__ float g_x1[(size_t)512 * NTOT];   // unshifted, channel-major [h][n]
__device__ float g_x2[(size_t)512 * NTOT];
__device__ float g_emb[(size_t)256 * NTOT];
__device__ float g_stats[4 * BATCH];

__device__ __forceinline__ void cpa16(u32 s, const void* g) {
    asm volatile("cp.async.cg.shared.global [%0], [%1], 16;" :: "r"(s), "l"(g));
}
#define CPA_COMMIT() asm volatile("cp.async.commit_group;")
template<int N> __device__ __forceinline__ void cpa_wait() {
    asm volatile("cp.async.wait_group %0;" :: "n"(N));
}
__device__ __forceinline__ void ldsm4(u32* r, u32 addr) {
    asm volatile("ldmatrix.sync.aligned.m8n8.x4.shared.b16 {%0,%1,%2,%3}, [%4];"
        : "=r"(r[0]), "=r"(r[1]), "=r"(r[2]), "=r"(r[3]) : "r"(addr));
}
__device__ __forceinline__ void mma16816(float* c, const u32* a, const u32* b) {
    asm volatile("mma.sync.aligned.m16n8k16.row.col.f32.bf16.bf16.f32 "
        "{%0,%1,%2,%3}, {%4,%5,%6,%7}, {%8,%9}, {%0,%1,%2,%3};"
        : "+f"(c[0]), "+f"(c[1]), "+f"(c[2]), "+f"(c[3])
        : "r"(a[0]), "r"(a[1]), "r"(a[2]), "r"(a[3]), "r"(b[0]), "r"(b[1]));
}
__device__ __forceinline__ u32 pack2(float a, float b, u32& lo_out) {
    __nv_bfloat16 ha = __float2bfloat16(a), hb = __float2bfloat16(b);
    __nv_bfloat16 la = __float2bfloat16(a - __bfloat162float(ha));
    __nv_bfloat16 lb = __float2bfloat16(b - __bfloat162float(hb));
    lo_out = (u32)__bfloat16_as_ushort(la) | ((u32)__bfloat16_as_ushort(lb) << 16);
    return   (u32)__bfloat16_as_ushort(ha) | ((u32)__bfloat16_as_ushort(hb) << 16);
}

// ---------------- W split + K-pad: wh/wl[h][KPAD] ----------------
__global__ void wsplit_kernel(const float* __restrict__ w, __nv_bfloat16* __restrict__ wh,
                              __nv_bfloat16* __restrict__ wl, int K, int KPAD, int total)
{
    int e = blockIdx.x * 256 + threadIdx.x;
    if (e >= total) return;
    int h = e / KPAD, k = e - h * KPAD;
    float v = (k < K) ? w[(size_t)h * K + k] : 0.f;
    __nv_bfloat16 hi = __float2bfloat16(v);
    wh[e] = hi;
    wl[e] = __float2bfloat16(v - __bfloat162float(hi));
}

// ---------------- gather -> G[n][k] hi/lo bf16 ----------------
// MODE 0: in = trees [B][CIN][128], direct idx.
// MODE 1: in = x [CIN][NTOT] unshifted; idx==0 -> relu(-mean*inv) else normed x[idx-1].
template<int CCH, int KPAD, int MODE>
__global__ __launch_bounds__(128)
void gather_kernel(const float* __restrict__ in, const int* __restrict__ idxg,
                   const float* __restrict__ stats_in,
                   __nv_bfloat16* __restrict__ Gh, __nv_bfloat16* __restrict__ Gl, int CIN)
{
    const int b = blockIdx.y, blk = blockIdx.x, tid = threadIdx.x;
    const int c0 = blk * CCH;
    __shared__ int   idx_s[384];
    __shared__ float x_s[CCH * 128];

    float mean = 0.f, inv = 1.f, v0 = 0.f;
    if (MODE == 1) {
        float s  = stats_in[2 * b];
        float s2 = stats_in[2 * b + 1];
        const float N = 65536.f;
        float m   = s / N;
        float var = (s2 - s * s / N) * (1.f / 65535.f);
        mean = m;
        inv  = 1.f / (sqrtf(fmaxf(var, 0.f)) + 1e-5f);
        v0   = fmaxf(-mean * inv, 0.f);
    }
    for (int i = tid; i < 384; i += 128) idx_s[i] = (i < 381) ? idxg[b * 381 + i] : 0;

    for (int q = tid; q < CCH * 32; q += 128) {
        int cl = q >> 5, vq = q & 31;
        const float* src = (MODE == 0)
            ? in + ((size_t)b * CIN + c0 + cl) * 128 + vq * 4
            : in + (size_t)(c0 + cl) * NTOT + b * 128 + vq * 4;
        float4 v = *(const float4*)src;
        if (MODE == 1) {
            v.x = fmaxf((v.x - mean) * inv, 0.f);
            v.y = fmaxf((v.y - mean) * inv, 0.f);
            v.z = fmaxf((v.z - mean) * inv, 0.f);
            v.w = fmaxf((v.w - mean) * inv, 0.f);
        }
        *(float4*)&x_s[q * 4] = v;
    }
    __syncthreads();

    const int j = tid;
    const int i0 = idx_s[3 * j], i1 = idx_s[3 * j + 1], i2 = idx_s[3 * j + 2];
    const bool live = (j < 127);
    const int kreal = 3 * CCH;
    const int ktot = (blk == gridDim.x - 1) ? (KPAD - 3 * c0) : 3 * CCH;

    auto elem = [&](int e) -> float {
        if (!live || e >= kreal) return 0.f;
        int cl = e / 3, r = e - cl * 3;
        int ii = (r == 0) ? i0 : ((r == 1) ? i1 : i2);
        if (MODE == 0) return x_s[cl * 128 + ii];
        return ii ? x_s[cl * 128 + ii - 1] : v0;
    };

    const size_t rowoff = (size_t)(b * 128 + j) * KPAD + 3 * c0;
    uint4* dh = (uint4*)(Gh + rowoff);
    uint4* dl = (uint4*)(Gl + rowoff);
    const int NG = ktot >> 3;
    for (int g = 0; g < NG; g++) {
        u32 uh[4], ul[4];
        #pragma unroll
        for (int t = 0; t < 4; t++) {
            int e0 = g * 8 + 2 * t;
            uh[t] = pack2(elem(e0), elem(e0 + 1), ul[t]);
        }
        dh[g] = make_uint4(uh[0], uh[1], uh[2], uh[3]);
        dl[g] = make_uint4(ul[0], ul[1], ul[2], ul[3]);
    }
}

// ---------------- warp-MMA split-bf16 GEMM ----------------
// D[h0..h0+128)[n0..n0+128) = sum_k (Wh+Wl)[h][k]*(Gh+Gl)[n][k]  (3 passes)
// 256 thr = 8 warps (2m x 4n); warp tile 64m x 32n; k-tile 32, double-buffered.
// smem rows padded to 80B (40 bf16) -> conflict-free ldmatrix.
#define HSTAGE 40960         // 4 planes * 128 rows * 80B
#define HSMEM  (2 * HSTAGE)

template<int KPAD, int STATS>
__global__ __launch_bounds__(256)
void hmma_gemm_kernel(const __nv_bfloat16* __restrict__ Gh, const __nv_bfloat16* __restrict__ Gl,
                      const __nv_bfloat16* __restrict__ Wh, const __nv_bfloat16* __restrict__ Wl,
                      const float* __restrict__ bias, float* __restrict__ stats_out,
                      float* __restrict__ out)
{
    extern __shared__ char dsm[];
    __shared__ float bias_s[128];
    __shared__ float rsum[8], rsq[8];
    const int tid = threadIdx.x, wid = tid >> 5, lid = tid & 31;
    const int wm = wid & 1, wn = wid >> 1;
    const int h0 = blockIdx.x * 128;
    const int n0 = blockIdx.y * 128;       // one batch per CTA
    const u32 sbase = (u32)__cvta_generic_to_shared(dsm);

    if (tid < 128) bias_s[tid] = bias[h0 + tid];

    const __nv_bfloat16* pl[4] = {
        Wh + (size_t)h0 * KPAD, Wl + (size_t)h0 * KPAD,
        Gh + (size_t)n0 * KPAD, Gl + (size_t)n0 * KPAD };

    float acc[4][4][4];
    #pragma unroll
    for (int mi = 0; mi < 4; mi++)
        #pragma unroll
        for (int ni = 0; ni < 4; ni++)
            #pragma unroll
            for (int r = 0; r < 4; r++) acc[mi][ni][r] = 0.f;

    auto stage = [&](int c, int st) {
        int k0 = c * 32;
        u32 sb = sbase + st * HSTAGE;
        #pragma unroll
        for (int i = 0; i < 8; i++) {
            int q = tid + i * 256;                  // 0..2047
            int plane = q >> 9, rem = q & 511, row = rem >> 2, kc = rem & 3;
            u32 dst = sb + plane * 10240 + row * 80 + kc * 16;
            cpa16(dst, pl[plane] + (size_t)row * KPAD + k0 + kc * 8);
        }
        CPA_COMMIT();
    };

    constexpr int NC = KPAD / 32;
    stage(0, 0);
    for (int c = 0; c < NC; c++) {
        int st = c & 1;
        if (c + 1 < NC) { stage(c + 1, st ^ 1); cpa_wait<1>(); }
        else            { cpa_wait<0>(); }
        __syncthreads();
        u32 sw0 = sbase + st * HSTAGE;
        #pragma unroll
        for (int s2 = 0; s2 < 2; s2++) {
            u32 ah[4][4], al[4][4], bh2[4][2], bl2[4][2];
            int gAr = ((lid >> 3) & 1) * 8 + (lid & 7);
            int gAb = (lid >> 4) * 16 + s2 * 32;
            #pragma unroll
            for (int mi = 0; mi < 4; mi++) {
                int row = wm * 64 + mi * 16 + gAr;
                ldsm4(ah[mi], sw0 + row * 80 + gAb);
                ldsm4(al[mi], sw0 + 10240 + row * 80 + gAb);
            }
            int gBr = (lid >> 4) * 8 + (lid & 7);
            int gBb = ((lid >> 3) & 1) * 16 + s2 * 32;
            #pragma unroll
            for (int t = 0; t < 2; t++) {
                int row = wn * 32 + t * 16 + gBr;
                u32 r4[4];
                ldsm4(r4, sw0 + 20480 + row * 80 + gBb);
                bh2[2 * t][0] = r4[0]; bh2[2 * t][1] = r4[1];
                bh2[2 * t + 1][0] = r4[2]; bh2[2 * t + 1][1] = r4[3];
                ldsm4(r4, sw0 + 30720 + row * 80 + gBb);
                bl2[2 * t][0] = r4[0]; bl2[2 * t][1] = r4[1];
                bl2[2 * t + 1][0] = r4[2]; bl2[2 * t + 1][1] = r4[3];
            }
            #pragma unroll
            for (int mi = 0; mi < 4; mi++)
                #pragma unroll
                for (int ni = 0; ni < 4; ni++) mma16816(acc[mi][ni], ah[mi], bh2[ni]);
            #pragma unroll
            for (int mi = 0; mi < 4; mi++)
                #pragma unroll
                for (int ni = 0; ni < 4; ni++) mma16816(acc[mi][ni], ah[mi], bl2[ni]);
            #pragma unroll
            for (int mi = 0; mi < 4; mi++)
                #pragma unroll
                for (int ni = 0; ni < 4; ni++) mma16816(acc[mi][ni], al[mi], bh2[ni]);
        }
        __syncthreads();
    }

    // epilogue: bias + col127->0 + stats + coalesced-ish float2 stores
    float lsum = 0.f, lsq = 0.f;
    #pragma unroll
    for (int mi = 0; mi < 4; mi++) {
        #pragma unroll
        for (int ni = 0; ni < 4; ni++) {
            float* cf = acc[mi][ni];
            int hb = h0 + wm * 64 + mi * 16 + (lid >> 2);
            int nb = n0 + wn * 32 + ni * 8 + (lid & 3) * 2;
            int j0 = nb & 127;
            #pragma unroll
            for (int half = 0; half < 2; half++) {
                int h = hb + half * 8;
                float bb = bias_s[h - h0];
                float v0 = cf[half * 2 + 0] + bb;
                float v1 = (j0 == 126) ? 0.f : cf[half * 2 + 1] + bb;
                if (STATS) { lsum += v0 + v1; lsq += v0 * v0 + v1 * v1; }
                float2 st2 = make_float2(v0, v1);
                *(float2*)(out + (size_t)h * NTOT + nb) = st2;
            }
        }
    }
    if (STATS) {
        #pragma unroll
        for (int o = 16; o > 0; o >>= 1) {
            lsum += __shfl_xor_sync(0xffffffffu, lsum, o);
            lsq  += __shfl_xor_sync(0xffffffffu, lsq,  o);
        }
        if (lid == 0) { rsum[wid] = lsum; rsq[wid] = lsq; }
        __syncthreads();
        if (tid == 0) {
            float a = 0.f, c2 = 0.f;
            #pragma unroll
            for (int i = 0; i < 8; i++) { a += rsum[i]; c2 += rsq[i]; }
            atomicAdd(&stats_out[2 * blockIdx.y],     a);
            atomicAdd(&stats_out[2 * blockIdx.y + 1], c2);
        }
    }
}

// ---------------- fp32x2 helpers (gate kernel) ----------------
__device__ __forceinline__ u64 fma2(u64 a, u64 b, u64 c) {
    u64 d;
    asm("fma.rn.f32x2 %0, %1, %2, %3;" : "=l"(d) : "l"(a), "l"(b), "l"(c));
    return d;
}
__device__ __forceinline__ u64 rep2(float x) {
    u64 d;
    asm("mov.b64 %0, {%1, %1};" : "=l"(d) : "f"(x));
    return d;
}
__device__ __forceinline__ float2 unpk(u64 a) {
    float2 r;
    asm("mov.b64 {%0, %1}, %2;" : "=f"(r.x), "=f"(r.y) : "l"(a));
    return r;
}

// ---------------- gate + softmax + pool + combined (emb [f][NTOT] unshifted) --
#define GATE_SMEM_FLOATS (256 * 132 + 32 * 130 + 16 * 128 + 128 + 8)
__global__ __launch_bounds__(512, 1)
void gate_kernel(const float* __restrict__ emb, const float* __restrict__ gw1,
                 const float* __restrict__ gb1, const float* __restrict__ gw2,
                 const float* __restrict__ gb2, float* __restrict__ comb)
{
    extern __shared__ float sm[];
    float* et     = sm;                    // [256][132] shifted view, f-major
    float* wc     = et + 256 * 132;
    float* red    = wc + 32 * 130;
    float* logits = red + 16 * 128;
    float* rtmp   = logits + 128;

    int b = blockIdx.x, tid = threadIdx.x;
    int tx = tid & 31, ty = tid >> 5;
    const float* eb = emb + (size_t)b * 128;

    for (int q = tid; q < 256 * 32; q += 512) {
        int f = q >> 5, nq = q & 31;
        float4 v = *(const float4*)(eb + (size_t)f * NTOT + nq * 4);
        float* d = &et[f * 132 + nq * 4 + 1];
        d[0] = v.x; d[1] = v.y; d[2] = v.z; d[3] = v.w;
        if (nq == 0) et[f * 132] = 0.f;
    }

    u64 acc[4][4];
    const u64* gb1p = (const u64*)gb1;
    #pragma unroll
    for (int p = 0; p < 4; p++) {
        u64 bp = gb1p[ty * 4 + p];
        #pragma unroll
        for (int u = 0; u < 4; u++) acc[p][u] = bp;
    }
    __syncthreads();

    for (int fc = 0; fc < 256; fc += 32) {
        for (int q = tid; q < 1024; q += 512) {
            int h = q >> 3, flq = q & 7;
            float4 v = *(const float4*)(gw1 + h * 256 + fc + flq * 4);
            wc[(flq * 4 + 0) * 130 + h] = v.x;
            wc[(flq * 4 + 1) * 130 + h] = v.y;
            wc[(flq * 4 + 2) * 130 + h] = v.z;
            wc[(flq * 4 + 3) * 130 + h] = v.w;
        }
        __syncthreads();
        #pragma unroll 4
        for (int fl = 0; fl < 32; fl++) {
            const u64* wp = (const u64*)&wc[fl * 130 + ty * 8];
            u64 wv[4] = {wp[0], wp[1], wp[2], wp[3]};
            float4 g4 = *(const float4*)&et[(fc + fl) * 132 + tx * 4];
            u64 gp0 = rep2(g4.x), gp1 = rep2(g4.y), gp2 = rep2(g4.z), gp3 = rep2(g4.w);
            #pragma unroll
            for (int p = 0; p < 4; p++) {
                acc[p][0] = fma2(wv[p], gp0, acc[p][0]);
                acc[p][1] = fma2(wv[p], gp1, acc[p][1]);
                acc[p][2] = fma2(wv[p], gp2, acc[p][2]);
                acc[p][3] = fma2(wv[p], gp3, acc[p][3]);
            }
        }
        __syncthreads();
    }

    const u64* gw2p = (const u64*)gw2;
    float part[4] = {0.f, 0.f, 0.f, 0.f};
    #pragma unroll
    for (int p = 0; p < 4; p++) {
        float2 wv = unpk(gw2p[ty * 4 + p]);
        #pragma unroll
        for (int u = 0; u < 4; u++) {
            float2 v = unpk(acc[p][u]);
            part[u] += fmaxf(v.x, 0.f) * wv.x + fmaxf(v.y, 0.f) * wv.y;
        }
    }
    #pragma unroll
    for (int u = 0; u < 4; u++) red[ty * 128 + tx * 4 + u] = part[u];
    __syncthreads();

    if (tid < 128) {
        float s = gb2[0];
        #pragma unroll
        for (int t = 0; t < 16; t++) s += red[t * 128 + tid];
        logits[tid] = s;
    }
    __syncthreads();
    if (tid < 128) {
        float v = logits[tid];
        for (int o = 16; o > 0; o >>= 1) v = fmaxf(v, __shfl_xor_sync(0xffffffffu, v, o));
        if ((tid & 31) == 0) rtmp[tid >> 5] = v;
    }
    __syncthreads();
    float gmax = fmaxf(fmaxf(rtmp[0], rtmp[1]), fmaxf(rtmp[2], rtmp[3]));
    if (tid < 128) logits[tid] = expf(logits[tid] - gmax);
    __syncthreads();
    if (tid < 128) {
        float v = logits[tid];
        for (int o = 16; o > 0; o >>= 1) v += __shfl_xor_sync(0xffffffffu, v, o);
        if ((tid & 31) == 0) rtmp[4 + (tid >> 5)] = v;
    }
    __syncthreads();
    float rinv = 1.f / (rtmp[4] + rtmp[5] + rtmp[6] + rtmp[7]);
    if (tid < 128) logits[tid] *= rinv;
    __syncthreads();

    if (tid < 256) {
        int f = tid;
        float pv = 0.f;
        #pragma unroll 8
        for (int n = 0; n < 128; n++) pv += logits[n] * et[f * 132 + n];
        comb[(size_t)b * 512 + f]       = et[f * 132 + 1];
        comb[(size_t)b * 512 + 256 + f] = pv;
    }
}

// ---------------- tiny MLP head ----------------
__global__ __launch_bounds__(128)
void head_kernel(const float* __restrict__ comb,
                 const float* __restrict__ rw1, const float* __restrict__ rb1,
                 const float* __restrict__ rw2, const float* __restrict__ rb2,
                 const float* __restrict__ rw3, const float* __restrict__ rb3,
                 float* __restrict__ outv)
{
    __shared__ float cs[512];
    __shared__ float wcs[128][33];
    __shared__ float h1[128];
    __shared__ float h2[64];
    int b = blockIdx.x, tid = threadIdx.x;

    for (int i = tid; i < 512; i += 128) cs[i] = comb[(size_t)b * 512 + i];

    float a = rb1[tid];
    for (int i0 = 0; i0 < 512; i0 += 32) {
        for (int e = tid; e < 128 * 32; e += 128) {
            int h = e >> 5, il = e & 31;
            wcs[h][il] = rw1[h * 512 + i0 + il];
        }
        __syncthreads();
        #pragma unroll
        for (int il = 0; il < 32; il++) a += cs[i0 + il] * wcs[tid][il];
        __syncthreads();
    }
    h1[tid] = fmaxf(a, 0.f);
    __syncthreads();

    float a2 = (tid < 64) ? rb2[tid] : 0.f;
    for (int i0 = 0; i0 < 128; i0 += 32) {
        for (int e = tid; e < 64 * 32; e += 128) {
            int h = e >> 5, il = e & 31;
            wcs[h][il] = rw2[h * 128 + i0 + il];
        }
        __syncthreads();
        if (tid < 64) {
            #pragma unroll
            for (int il = 0; il < 32; il++) a2 += h1[i0 + il] * wcs[tid][il];
        }
        __syncthreads();
    }
    if (tid < 64) h2[tid] = fmaxf(a2, 0.f);
    __syncthreads();

    if (tid < 64) {
        float p = h2[tid] * rw3[tid];
        for (int o = 16; o > 0; o >>= 1) p += __shfl_xor_sync(0xffffffffu, p, o);
        if ((tid & 31) == 0) h1[64 + (tid >> 5)] = p;
    }
    __syncthreads();
    if (tid == 0) outv[b] = h1[64] + h1[65] + rb3[0];
}

// ---------------- launch ----------------
extern "C" void kernel_launch(void* const* d_in, const int* in_sizes, int n_in,
                              void* d_out, int out_size)
{
    const float* trees = (const float*)d_in[0];
    const int*   idx   = (const int*)  d_in[1];
    const float* w1    = (const float*)d_in[2];
    const float* b1    = (const float*)d_in[3];
    const float* w2    = (const float*)d_in[4];
    const float* b2    = (const float*)d_in[5];
    const float* w3    = (const float*)d_in[6];
    const float* b3    = (const float*)d_in[7];
    const float* gw1   = (const float*)d_in[8];
    const float* gb1   = (const float*)d_in[9];
    const float* gw2   = (const float*)d_in[10];
    const float* gb2   = (const float*)d_in[11];
    const float* rw1   = (const float*)d_in[12];
    const float* rb1   = (const float*)d_in[13];
    const float* rw2   = (const float*)d_in[14];
    const float* rb2   = (const float*)d_in[15];
    const float* rw3   = (const float*)d_in[16];
    const float* rb3   = (const float*)d_in[17];

    float* out  = (float*)d_out;
    float* comb = out + 512;

    float *x1, *x2, *embp, *st;
    __nv_bfloat16 *Gh, *Gl, *Wh, *Wl;
    cudaGetSymbolAddress((void**)&x1,   g_x1);
    cudaGetSymbolAddress((void**)&x2,   g_x2);
    cudaGetSymbolAddress((void**)&embp, g_emb);
    cudaGetSymbolAddress((void**)&Gh,   g_Ghi);
    cudaGetSymbolAddress((void**)&Gl,   g_Glo);
    cudaGetSymbolAddress((void**)&Wh,   g_Whi);
    cudaGetSymbolAddress((void**)&Wl,   g_Wlo);
    cudaGetSymbolAddress((void**)&st,   g_stats);
    __nv_bfloat16* Wh1 = Wh;               __nv_bfloat16* Wl1 = Wl;
    __nv_bfloat16* Wh2 = Wh + 512 * 640;   __nv_bfloat16* Wl2 = Wl + 512 * 640;
    __nv_bfloat16* Wh3 = Wh2 + 512 * 1536; __nv_bfloat16* Wl3 = Wl2 + 512 * 1536;
    float* st1 = st;
    float* st2 = st + 2 * BATCH;

    cudaFuncSetAttribute(hmma_gemm_kernel<640, 1>,  cudaFuncAttributeMaxDynamicSharedMemorySize, HSMEM);
    cudaFuncSetAttribute(hmma_gemm_kernel<1536, 1>, cudaFuncAttributeMaxDynamicSharedMemorySize, HSMEM);
    cudaFuncSetAttribute(hmma_gemm_kernel<1536, 0>, cudaFuncAttributeMaxDynamicSharedMemorySize, HSMEM);
    size_t gate_smem = (size_t)GATE_SMEM_FLOATS * sizeof(float);
    cudaFuncSetAttribute(gate_kernel, cudaFuncAttributeMaxDynamicSharedMemorySize, (int)gate_smem);

    cudaMemsetAsync(st, 0, 4 * BATCH * sizeof(float));

    wsplit_kernel<<<(512 * 640  + 255) / 256, 256>>>(w1, Wh1, Wl1, 600,  640,  512 * 640);
    wsplit_kernel<<<(512 * 1536 + 255) / 256, 256>>>(w2, Wh2, Wl2, 1536, 1536, 512 * 1536);
    wsplit_kernel<<<(256 * 1536 + 255) / 256, 256>>>(w3, Wh3, Wl3, 1536, 1536, 256 * 1536);

    // layer 1
    gather_kernel<40, 640, 0><<<dim3(5, BATCH), 128>>>(trees, idx, nullptr, Gh, Gl, 200);
    hmma_gemm_kernel<640, 1><<<dim3(4, BATCH), 256, HSMEM>>>(Gh, Gl, Wh1, Wl1, b1, st1, x1);
    // layer 2
    gather_kernel<64, 1536, 1><<<dim3(8, BATCH), 128>>>(x1, idx, st1, Gh, Gl, 512);
    hmma_gemm_kernel<1536, 1><<<dim3(4, BATCH), 256, HSMEM>>>(Gh, Gl, Wh2, Wl2, b2, st2, x2);
    // layer 3
    gather_kernel<64, 1536, 1><<<dim3(8, BATCH), 128>>>(x2, idx, st2, Gh, Gl, 512);
    hmma_gemm_kernel<1536, 0><<<dim3(2, BATCH), 256, HSMEM>>>(Gh, Gl, Wh3, Wl3, b3, nullptr, embp);
    // pool + head
    gate_kernel<<<BATCH, 512, gate_smem>>>(embp, gw1, gb1, gw2, gb2, comb);
    head_kernel<<<BATCH, 128>>>(comb, rw1, rb1, rw2, rb2, rw3, rb3, out);
}

// round 7
// speedup vs baseline: 3.3086x; 1.3052x over previous
#include <cuda_runtime.h>
#include <cuda_bf16.h>
#include <math.h>
#include <stdint.h>

#define BATCH 512
#define NTOT  65536
typedef unsigned long long u64;
typedef unsigned int u32;

// ---------------- scratch (device globals) ----------------
__device__ __nv_bfloat16 g_Ghi[(size_t)NTOT * 1536];
__device__ __nv_bfloat16 g_Glo[(size_t)NTOT * 1536];
__device__ __nv_bfloat16 g_Whi[512 * 640 + 512 * 1536 + 256 * 1536];
__device__ __nv_bfloat16 g_Wlo[512 * 640 + 512 * 1536 + 256 * 1536];
__device__ float g_x1[(size_t)512 * NTOT];   // unshifted, channel-major [h][n]
__device__ float g_x2[(size_t)512 * NTOT];
__device__ float g_emb[(size_t)256 * NTOT];
__device__ float g_stats[4 * BATCH];

__device__ __forceinline__ void cpa16(u32 s, const void* g) {
    asm volatile("cp.async.cg.shared.global [%0], [%1], 16;" :: "r"(s), "l"(g));
}
#define CPA_COMMIT() asm volatile("cp.async.commit_group;")
template<int N> __device__ __forceinline__ void cpa_wait() {
    asm volatile("cp.async.wait_group %0;" :: "n"(N));
}
__device__ __forceinline__ void ldsm4(u32* r, u32 addr) {
    asm volatile("ldmatrix.sync.aligned.m8n8.x4.shared.b16 {%0,%1,%2,%3}, [%4];"
        : "=r"(r[0]), "=r"(r[1]), "=r"(r[2]), "=r"(r[3]) : "r"(addr));
}
__device__ __forceinline__ void mma16816(float* c, const u32* a, const u32* b) {
    asm volatile("mma.sync.aligned.m16n8k16.row.col.f32.bf16.bf16.f32 "
        "{%0,%1,%2,%3}, {%4,%5,%6,%7}, {%8,%9}, {%0,%1,%2,%3};"
        : "+f"(c[0]), "+f"(c[1]), "+f"(c[2]), "+f"(c[3])
        : "r"(a[0]), "r"(a[1]), "r"(a[2]), "r"(a[3]), "r"(b[0]), "r"(b[1]));
}
__device__ __forceinline__ u32 pack2(float a, float b, u32& lo_out) {
    __nv_bfloat16 ha = __float2bfloat16(a), hb = __float2bfloat16(b);
    __nv_bfloat16 la = __float2bfloat16(a - __bfloat162float(ha));
    __nv_bfloat16 lb = __float2bfloat16(b - __bfloat162float(hb));
    lo_out = (u32)__bfloat16_as_ushort(la) | ((u32)__bfloat16_as_ushort(lb) << 16);
    return   (u32)__bfloat16_as_ushort(ha) | ((u32)__bfloat16_as_ushort(hb) << 16);
}

// ---------------- W split + K-pad: wh/wl[h][KPAD] ----------------
__global__ void wsplit_kernel(const float* __restrict__ w, __nv_bfloat16* __restrict__ wh,
                              __nv_bfloat16* __restrict__ wl, int K, int KPAD, int total)
{
    int e = blockIdx.x * 256 + threadIdx.x;
    if (e >= total) return;
    int h = e / KPAD, k = e - h * KPAD;
    float v = (k < K) ? w[(size_t)h * K + k] : 0.f;
    __nv_bfloat16 hi = __float2bfloat16(v);
    wh[e] = hi;
    wl[e] = __float2bfloat16(v - __bfloat162float(hi));
}

// ---------------- gather v3: warp-per-row, coalesced u32 stores ----------------
// G[b*128+j][kbase + k] = T(x at idx), packed bf16 hi/lo planes.
// MODE 0: in = trees [B][CIN][128], direct idx.
// MODE 1: in = x [CIN][NTOT] unshifted; idx==0 -> relu(-mean*inv), else normed x[idx-1].
#define XPAD 132
template<int CCH, int KPAD, int MODE>
__global__ __launch_bounds__(256)
void gather_kernel(const float* __restrict__ in, const int* __restrict__ idxg,
                   const float* __restrict__ stats_in,
                   __nv_bfloat16* __restrict__ Gh, __nv_bfloat16* __restrict__ Gl, int CIN)
{
    const int b = blockIdx.y, blk = blockIdx.x, tid = threadIdx.x;
    const int c0 = blk * CCH;
    const int kbase = 3 * c0;
    const int klen = (KPAD - kbase < 3 * CCH) ? (KPAD - kbase) : (3 * CCH);
    __shared__ int   idx_s[384];
    __shared__ float x_s[CCH * XPAD];

    float mean = 0.f, inv = 1.f, v0 = 0.f;
    if (MODE == 1) {
        float s  = stats_in[2 * b];
        float s2 = stats_in[2 * b + 1];
        const float N = 65536.f;
        float m   = s / N;
        float var = (s2 - s * s / N) * (1.f / 65535.f);
        mean = m;
        inv  = 1.f / (sqrtf(fmaxf(var, 0.f)) + 1e-5f);
        v0   = fmaxf(-mean * inv, 0.f);
    }
    for (int i = tid; i < 384; i += 256) idx_s[i] = (i < 381) ? idxg[b * 381 + i] : 0;

    for (int q = tid; q < CCH * 32; q += 256) {
        int cl = q >> 5, vq = q & 31;
        float4 v = make_float4(0.f, 0.f, 0.f, 0.f);
        if (c0 + cl < CIN) {
            const float* src = (MODE == 0)
                ? in + ((size_t)b * CIN + c0 + cl) * 128 + vq * 4
                : in + (size_t)(c0 + cl) * NTOT + b * 128 + vq * 4;
            v = *(const float4*)src;
            if (MODE == 1) {
                v.x = fmaxf((v.x - mean) * inv, 0.f);
                v.y = fmaxf((v.y - mean) * inv, 0.f);
                v.z = fmaxf((v.z - mean) * inv, 0.f);
                v.w = fmaxf((v.w - mean) * inv, 0.f);
            }
        }
        *(float4*)&x_s[cl * XPAD + vq * 4] = v;
    }
    __syncthreads();

    const int wid = tid >> 5, lane = tid & 31;

    for (int j = wid; j < 128; j += 8) {
        const int i0 = idx_s[3 * j], i1 = idx_s[3 * j + 1], i2 = idx_s[3 * j + 2];
        const bool live = (j < 127);
        // per-tap value fetch (local element index e in [0, klen))
        auto elem = [&](int e) -> float {
            if (!live) return 0.f;
            int cl = e / 3, r = e - 3 * cl;
            int ii = (r == 0) ? i0 : ((r == 1) ? i1 : i2);
            if (MODE == 0) return x_s[cl * XPAD + ii];
            return ii ? x_s[cl * XPAD + ii - 1] : v0;
        };
        const size_t wbase = ((size_t)(b * 128 + j) * KPAD + kbase) >> 1;  // u32 index
        for (int kp = lane; 2 * kp < klen; kp += 32) {
            int e0 = 2 * kp;
            u32 lo;
            u32 hi = pack2(elem(e0), elem(e0 + 1), lo);
            ((u32*)Gh)[wbase + kp] = hi;
            ((u32*)Gl)[wbase + kp] = lo;
        }
    }
}

// ---------------- warp-MMA split-bf16 GEMM ----------------
// D[h0..h0+128)[n0..n0+128) = sum_k (Wh+Wl)[h][k]*(Gh+Gl)[n][k]  (3 passes)
// 256 thr = 8 warps (2m x 4n); warp tile 64m x 32n; k-tile 32, double-buffered.
// smem rows padded to 80B (40 bf16) -> conflict-free ldmatrix.
#define HSTAGE 40960         // 4 planes * 128 rows * 80B
#define HSMEM  (2 * HSTAGE)

template<int KPAD, int STATS>
__global__ __launch_bounds__(256)
void hmma_gemm_kernel(const __nv_bfloat16* __restrict__ Gh, const __nv_bfloat16* __restrict__ Gl,
                      const __nv_bfloat16* __restrict__ Wh, const __nv_bfloat16* __restrict__ Wl,
                      const float* __restrict__ bias, float* __restrict__ stats_out,
                      float* __restrict__ out)
{
    extern __shared__ char dsm[];
    __shared__ float bias_s[128];
    __shared__ float rsum[8], rsq[8];
    const int tid = threadIdx.x, wid = tid >> 5, lid = tid & 31;
    const int wm = wid & 1, wn = wid >> 1;
    const int h0 = blockIdx.x * 128;
    const int n0 = blockIdx.y * 128;       // one batch per CTA
    const u32 sbase = (u32)__cvta_generic_to_shared(dsm);

    if (tid < 128) bias_s[tid] = bias[h0 + tid];

    const __nv_bfloat16* pl[4] = {
        Wh + (size_t)h0 * KPAD, Wl + (size_t)h0 * KPAD,
        Gh + (size_t)n0 * KPAD, Gl + (size_t)n0 * KPAD };

    float acc[4][4][4];
    #pragma unroll
    for (int mi = 0; mi < 4; mi++)
        #pragma unroll
        for (int ni = 0; ni < 4; ni++)
            #pragma unroll
            for (int r = 0; r < 4; r++) acc[mi][ni][r] = 0.f;

    auto stage = [&](int c, int st) {
        int k0 = c * 32;
        u32 sb = sbase + st * HSTAGE;
        #pragma unroll
        for (int i = 0; i < 8; i++) {
            int q = tid + i * 256;                  // 0..2047
            int plane = q >> 9, rem = q & 511, row = rem >> 2, kc = rem & 3;
            u32 dst = sb + plane * 10240 + row * 80 + kc * 16;
            cpa16(dst, pl[plane] + (size_t)row * KPAD + k0 + kc * 8);
        }
        CPA_COMMIT();
    };

    constexpr int NC = KPAD / 32;
    stage(0, 0);
    for (int c = 0; c < NC; c++) {
        int st = c & 1;
        if (c + 1 < NC) { stage(c + 1, st ^ 1); cpa_wait<1>(); }
        else            { cpa_wait<0>(); }
        __syncthreads();
        u32 sw0 = sbase + st * HSTAGE;
        #pragma unroll
        for (int s2 = 0; s2 < 2; s2++) {
            u32 ah[4][4], al[4][4], bh2[4][2], bl2[4][2];
            int gAr = ((lid >> 3) & 1) * 8 + (lid & 7);
            int gAb = (lid >> 4) * 16 + s2 * 32;
            #pragma unroll
            for (int mi = 0; mi < 4; mi++) {
                int row = wm * 64 + mi * 16 + gAr;
                ldsm4(ah[mi], sw0 + row * 80 + gAb);
                ldsm4(al[mi], sw0 + 10240 + row * 80 + gAb);
            }
            int gBr = (lid >> 4) * 8 + (lid & 7);
            int gBb = ((lid >> 3) & 1) * 16 + s2 * 32;
            #pragma unroll
            for (int t = 0; t < 2; t++) {
                int row = wn * 32 + t * 16 + gBr;
                u32 r4[4];
                ldsm4(r4, sw0 + 20480 + row * 80 + gBb);
                bh2[2 * t][0] = r4[0]; bh2[2 * t][1] = r4[1];
                bh2[2 * t + 1][0] = r4[2]; bh2[2 * t + 1][1] = r4[3];
                ldsm4(r4, sw0 + 30720 + row * 80 + gBb);
                bl2[2 * t][0] = r4[0]; bl2[2 * t][1] = r4[1];
                bl2[2 * t + 1][0] = r4[2]; bl2[2 * t + 1][1] = r4[3];
            }
            #pragma unroll
            for (int mi = 0; mi < 4; mi++)
                #pragma unroll
                for (int ni = 0; ni < 4; ni++) mma16816(acc[mi][ni], ah[mi], bh2[ni]);
            #pragma unroll
            for (int mi = 0; mi < 4; mi++)
                #pragma unroll
                for (int ni = 0; ni < 4; ni++) mma16816(acc[mi][ni], ah[mi], bl2[ni]);
            #pragma unroll
            for (int mi = 0; mi < 4; mi++)
                #pragma unroll
                for (int ni = 0; ni < 4; ni++) mma16816(acc[mi][ni], al[mi], bh2[ni]);
        }
        __syncthreads();
    }

    // epilogue: bias + col127->0 + stats + float2 stores
    float lsum = 0.f, lsq = 0.f;
    #pragma unroll
    for (int mi = 0; mi < 4; mi++) {
        #pragma unroll
        for (int ni = 0; ni < 4; ni++) {
            float* cf = acc[mi][ni];
            int hb = h0 + wm * 64 + mi * 16 + (lid >> 2);
            int nb = n0 + wn * 32 + ni * 8 + (lid & 3) * 2;
            int j0 = nb & 127;
            #pragma unroll
            for (int half = 0; half < 2; half++) {
                int h = hb + half * 8;
                float bb = bias_s[h - h0];
                float v0 = cf[half * 2 + 0] + bb;
                float v1 = (j0 == 126) ? 0.f : cf[half * 2 + 1] + bb;
                if (STATS) { lsum += v0 + v1; lsq += v0 * v0 + v1 * v1; }
                float2 st2 = make_float2(v0, v1);
                *(float2*)(out + (size_t)h * NTOT + nb) = st2;
            }
        }
    }
    if (STATS) {
        #pragma unroll
        for (int o = 16; o > 0; o >>= 1) {
            lsum += __shfl_xor_sync(0xffffffffu, lsum, o);
            lsq  += __shfl_xor_sync(0xffffffffu, lsq,  o);
        }
        if (lid == 0) { rsum[wid] = lsum; rsq[wid] = lsq; }
        __syncthreads();
        if (tid == 0) {
            float a = 0.f, c2 = 0.f;
            #pragma unroll
            for (int i = 0; i < 8; i++) { a += rsum[i]; c2 += rsq[i]; }
            atomicAdd(&stats_out[2 * blockIdx.y],     a);
            atomicAdd(&stats_out[2 * blockIdx.y + 1], c2);
        }
    }
}

// ---------------- fp32x2 helpers (gate kernel) ----------------
__device__ __forceinline__ u64 fma2(u64 a, u64 b, u64 c) {
    u64 d;
    asm("fma.rn.f32x2 %0, %1, %2, %3;" : "=l"(d) : "l"(a), "l"(b), "l"(c));
    return d;
}
__device__ __forceinline__ u64 rep2(float x) {
    u64 d;
    asm("mov.b64 %0, {%1, %1};" : "=l"(d) : "f"(x));
    return d;
}
__device__ __forceinline__ float2 unpk(u64 a) {
    float2 r;
    asm("mov.b64 {%0, %1}, %2;" : "=f"(r.x), "=f"(r.y) : "l"(a));
    return r;
}

// ---------------- gate + softmax + pool + combined (emb [f][NTOT] unshifted) --
#define GATE_SMEM_FLOATS (256 * 132 + 32 * 130 + 16 * 128 + 128 + 8)
__global__ __launch_bounds__(512, 1)
void gate_kernel(const float* __restrict__ emb, const float* __restrict__ gw1,
                 const float* __restrict__ gb1, const float* __restrict__ gw2,
                 const float* __restrict__ gb2, float* __restrict__ comb)
{
    extern __shared__ float sm[];
    float* et     = sm;                    // [256][132] shifted view, f-major
    float* wc     = et + 256 * 132;
    float* red    = wc + 32 * 130;
    float* logits = red + 16 * 128;
    float* rtmp   = logits + 128;

    int b = blockIdx.x, tid = threadIdx.x;
    int tx = tid & 31, ty = tid >> 5;
    const float* eb = emb + (size_t)b * 128;

    for (int q = tid; q < 256 * 32; q += 512) {
        int f = q >> 5, nq = q & 31;
        float4 v = *(const float4*)(eb + (size_t)f * NTOT + nq * 4);
        float* d = &et[f * 132 + nq * 4 + 1];
        d[0] = v.x; d[1] = v.y; d[2] = v.z; d[3] = v.w;
        if (nq == 0) et[f * 132] = 0.f;
    }

    u64 acc[4][4];
    const u64* gb1p = (const u64*)gb1;
    #pragma unroll
    for (int p = 0; p < 4; p++) {
        u64 bp = gb1p[ty * 4 + p];
        #pragma unroll
        for (int u = 0; u < 4; u++) acc[p][u] = bp;
    }
    __syncthreads();

    for (int fc = 0; fc < 256; fc += 32) {
        for (int q = tid; q < 1024; q += 512) {
            int h = q >> 3, flq = q & 7;
            float4 v = *(const float4*)(gw1 + h * 256 + fc + flq * 4);
            wc[(flq * 4 + 0) * 130 + h] = v.x;
            wc[(flq * 4 + 1) * 130 + h] = v.y;
            wc[(flq * 4 + 2) * 130 + h] = v.z;
            wc[(flq * 4 + 3) * 130 + h] = v.w;
        }
        __syncthreads();
        #pragma unroll 4
        for (int fl = 0; fl < 32; fl++) {
            const u64* wp = (const u64*)&wc[fl * 130 + ty * 8];
            u64 wv[4] = {wp[0], wp[1], wp[2], wp[3]};
            float4 g4 = *(const float4*)&et[(fc + fl) * 132 + tx * 4];
            u64 gp0 = rep2(g4.x), gp1 = rep2(g4.y), gp2 = rep2(g4.z), gp3 = rep2(g4.w);
            #pragma unroll
            for (int p = 0; p < 4; p++) {
                acc[p][0] = fma2(wv[p], gp0, acc[p][0]);
                acc[p][1] = fma2(wv[p], gp1, acc[p][1]);
                acc[p][2] = fma2(wv[p], gp2, acc[p][2]);
                acc[p][3] = fma2(wv[p], gp3, acc[p][3]);
            }
        }
        __syncthreads();
    }

    const u64* gw2p = (const u64*)gw2;
    float part[4] = {0.f, 0.f, 0.f, 0.f};
    #pragma unroll
    for (int p = 0; p < 4; p++) {
        float2 wv = unpk(gw2p[ty * 4 + p]);
        #pragma unroll
        for (int u = 0; u < 4; u++) {
            float2 v = unpk(acc[p][u]);
            part[u] += fmaxf(v.x, 0.f) * wv.x + fmaxf(v.y, 0.f) * wv.y;
        }
    }
    #pragma unroll
    for (int u = 0; u < 4; u++) red[ty * 128 + tx * 4 + u] = part[u];
    __syncthreads();

    if (tid < 128) {
        float s = gb2[0];
        #pragma unroll
        for (int t = 0; t < 16; t++) s += red[t * 128 + tid];
        logits[tid] = s;
    }
    __syncthreads();
    if (tid < 128) {
        float v = logits[tid];
        for (int o = 16; o > 0; o >>= 1) v = fmaxf(v, __shfl_xor_sync(0xffffffffu, v, o));
        if ((tid & 31) == 0) rtmp[tid >> 5] = v;
    }
    __syncthreads();
    float gmax = fmaxf(fmaxf(rtmp[0], rtmp[1]), fmaxf(rtmp[2], rtmp[3]));
    if (tid < 128) logits[tid] = expf(logits[tid] - gmax);
    __syncthreads();
    if (tid < 128) {
        float v = logits[tid];
        for (int o = 16; o > 0; o >>= 1) v += __shfl_xor_sync(0xffffffffu, v, o);
        if ((tid & 31) == 0) rtmp[4 + (tid >> 5)] = v;
    }
    __syncthreads();
    float rinv = 1.f / (rtmp[4] + rtmp[5] + rtmp[6] + rtmp[7]);
    if (tid < 128) logits[tid] *= rinv;
    __syncthreads();

    if (tid < 256) {
        int f = tid;
        float pv = 0.f;
        #pragma unroll 8
        for (int n = 0; n < 128; n++) pv += logits[n] * et[f * 132 + n];
        comb[(size_t)b * 512 + f]       = et[f * 132 + 1];
        comb[(size_t)b * 512 + 256 + f] = pv;
    }
}

// ---------------- tiny MLP head ----------------
__global__ __launch_bounds__(128)
void head_kernel(const float* __restrict__ comb,
                 const float* __restrict__ rw1, const float* __restrict__ rb1,
                 const float* __restrict__ rw2, const float* __restrict__ rb2,
                 const float* __restrict__ rw3, const float* __restrict__ rb3,
                 float* __restrict__ outv)
{
    __shared__ float cs[512];
    __shared__ float wcs[128][33];
    __shared__ float h1[128];
    __shared__ float h2[64];
    int b = blockIdx.x, tid = threadIdx.x;

    for (int i = tid; i < 512; i += 128) cs[i] = comb[(size_t)b * 512 + i];

    float a = rb1[tid];
    for (int i0 = 0; i0 < 512; i0 += 32) {
        for (int e = tid; e < 128 * 32; e += 128) {
            int h = e >> 5, il = e & 31;
            wcs[h][il] = rw1[h * 512 + i0 + il];
        }
        __syncthreads();
        #pragma unroll
        for (int il = 0; il < 32; il++) a += cs[i0 + il] * wcs[tid][il];
        __syncthreads();
    }
    h1[tid] = fmaxf(a, 0.f);
    __syncthreads();

    float a2 = (tid < 64) ? rb2[tid] : 0.f;
    for (int i0 = 0; i0 < 128; i0 += 32) {
        for (int e = tid; e < 64 * 32; e += 128) {
            int h = e >> 5, il = e & 31;
            wcs[h][il] = rw2[h * 128 + i0 + il];
        }
        __syncthreads();
        if (tid < 64) {
            #pragma unroll
            for (int il = 0; il < 32; il++) a2 += h1[i0 + il] * wcs[tid][il];
        }
        __syncthreads();
    }
    if (tid < 64) h2[tid] = fmaxf(a2, 0.f);
    __syncthreads();

    if (tid < 64) {
        float p = h2[tid] * rw3[tid];
        for (int o = 16; o > 0; o >>= 1) p += __shfl_xor_sync(0xffffffffu, p, o);
        if ((tid & 31) == 0) h1[64 + (tid >> 5)] = p;
    }
    __syncthreads();
    if (tid == 0) outv[b] = h1[64] + h1[65] + rb3[0];
}

// ---------------- launch ----------------
extern "C" void kernel_launch(void* const* d_in, const int* in_sizes, int n_in,
                              void* d_out, int out_size)
{
    const float* trees = (const float*)d_in[0];
    const int*   idx   = (const int*)  d_in[1];
    const float* w1    = (const float*)d_in[2];
    const float* b1    = (const float*)d_in[3];
    const float* w2    = (const float*)d_in[4];
    const float* b2    = (const float*)d_in[5];
    const float* w3    = (const float*)d_in[6];
    const float* b3    = (const float*)d_in[7];
    const float* gw1   = (const float*)d_in[8];
    const float* gb1   = (const float*)d_in[9];
    const float* gw2   = (const float*)d_in[10];
    const float* gb2   = (const float*)d_in[11];
    const float* rw1   = (const float*)d_in[12];
    const float* rb1   = (const float*)d_in[13];
    const float* rw2   = (const float*)d_in[14];
    const float* rb2   = (const float*)d_in[15];
    const float* rw3   = (const float*)d_in[16];
    const float* rb3   = (const float*)d_in[17];

    float* out  = (float*)d_out;
    float* comb = out + 512;

    float *x1, *x2, *embp, *st;
    __nv_bfloat16 *Gh, *Gl, *Wh, *Wl;
    cudaGetSymbolAddress((void**)&x1,   g_x1);
    cudaGetSymbolAddress((void**)&x2,   g_x2);
    cudaGetSymbolAddress((void**)&embp, g_emb);
    cudaGetSymbolAddress((void**)&Gh,   g_Ghi);
    cudaGetSymbolAddress((void**)&Gl,   g_Glo);
    cudaGetSymbolAddress((void**)&Wh,   g_Whi);
    cudaGetSymbolAddress((void**)&Wl,   g_Wlo);
    cudaGetSymbolAddress((void**)&st,   g_stats);
    __nv_bfloat16* Wh1 = Wh;               __nv_bfloat16* Wl1 = Wl;
    __nv_bfloat16* Wh2 = Wh + 512 * 640;   __nv_bfloat16* Wl2 = Wl + 512 * 640;
    __nv_bfloat16* Wh3 = Wh2 + 512 * 1536; __nv_bfloat16* Wl3 = Wl2 + 512 * 1536;
    float* st1 = st;
    float* st2 = st + 2 * BATCH;

    cudaFuncSetAttribute(hmma_gemm_kernel<640, 1>,  cudaFuncAttributeMaxDynamicSharedMemorySize, HSMEM);
    cudaFuncSetAttribute(hmma_gemm_kernel<1536, 1>, cudaFuncAttributeMaxDynamicSharedMemorySize, HSMEM);
    cudaFuncSetAttribute(hmma_gemm_kernel<1536, 0>, cudaFuncAttributeMaxDynamicSharedMemorySize, HSMEM);
    size_t gate_smem = (size_t)GATE_SMEM_FLOATS * sizeof(float);
    cudaFuncSetAttribute(gate_kernel, cudaFuncAttributeMaxDynamicSharedMemorySize, (int)gate_smem);

    cudaMemsetAsync(st, 0, 4 * BATCH * sizeof(float));

    wsplit_kernel<<<(512 * 640  + 255) / 256, 256>>>(w1, Wh1, Wl1, 600,  640,  512 * 640);
    wsplit_kernel<<<(512 * 1536 + 255) / 256, 256>>>(w2, Wh2, Wl2, 1536, 1536, 512 * 1536);
    wsplit_kernel<<<(256 * 1536 + 255) / 256, 256>>>(w3, Wh3, Wl3, 1536, 1536, 256 * 1536);

    // layer 1  (CCH=40 -> 120 k per block; 6 blocks cover KPAD=640)
    gather_kernel<40, 640, 0><<<dim3(6, BATCH), 256>>>(trees, idx, nullptr, Gh, Gl, 200);
    hmma_gemm_kernel<640, 1><<<dim3(4, BATCH), 256, HSMEM>>>(Gh, Gl, Wh1, Wl1, b1, st1, x1);
    // layer 2  (CCH=64 -> 192 k per block; 8 blocks cover 1536)
    gather_kernel<64, 1536, 1><<<dim3(8, BATCH), 256>>>(x1, idx, st1, Gh, Gl, 512);
    hmma_gemm_kernel<1536, 1><<<dim3(4, BATCH), 256, HSMEM>>>(Gh, Gl, Wh2, Wl2, b2, st2, x2);
    // layer 3
    gather_kernel<64, 1536, 1><<<dim3(8, BATCH), 256>>>(x2, idx, st2, Gh, Gl, 512);
    hmma_gemm_kernel<1536, 0><<<dim3(2, BATCH), 256, HSMEM>>>(Gh, Gl, Wh3, Wl3, b3, nullptr, embp);
    // pool + head
    gate_kernel<<<BATCH, 512, gate_smem>>>(embp, gw1, gb1, gw2, gb2, comb);
    head_kernel<<<BATCH, 128>>>(comb, rw1, rb1, rw2, rb2, rw3, rb3, out);
}